// round 1
// baseline (speedup 1.0000x reference)
#include <cuda_runtime.h>
#include <cuda_bf16.h>
#include <cstdint>

// Problem constants (all exact, no bounds checks needed)
#define B_       16
#define H_       56
#define W_       56
#define C_       768
#define WS_      14
#define NH_      12
#define HD_      64
#define NTOK_    196        // WS*WS
#define NWIN_    256        // B * 4 * 4
#define M_ROWS   50176      // B*H*W
#define K_DIM    768
#define N_QKV    2304
#define N_PROJ   768

// Scratch (device globals — allocation-free rule)
__device__ float g_qkv[(size_t)M_ROWS * N_QKV];   // 462 MB
__device__ float g_o  [(size_t)M_ROWS * N_PROJ];  // 154 MB

// ---------------------------------------------------------------------------
// SGEMM (NT): C[m,n] = sum_k A[m,k] * Bt[n,k] + bias[n]
// 128x128 block tile, 8x8 per-thread microtile, BK=8, reg-prefetch buffer.
// Requires M%128==0, N%128==0, K%8==0 (all true here).
// ---------------------------------------------------------------------------
#define BM 128
#define BN 128
#define BK 8

__global__ __launch_bounds__(256, 2)
void sgemm_nt_bias(const float* __restrict__ A, const float* __restrict__ Bt,
                   const float* __restrict__ bias, float* __restrict__ C,
                   int M, int N, int K)
{
    __shared__ float As[BK][BM];
    __shared__ float Bs[BK][BN];

    const int tid = threadIdx.x;
    const int m0  = blockIdx.y * BM;
    const int n0  = blockIdx.x * BN;
    const int tx  = tid & 15;
    const int ty  = tid >> 4;

    // global-load assignment: 256 threads * float4 = 1024 floats = one 128x8 tile
    const int lrow  = tid >> 1;       // 0..127
    const int lhalf = tid & 1;        // k sub-offset 0 / 4

    const float* Aptr = A  + (size_t)(m0 + lrow) * K + lhalf * 4;
    const float* Bptr = Bt + (size_t)(n0 + lrow) * K + lhalf * 4;

    float4 aReg = *(const float4*)Aptr;
    float4 bReg = *(const float4*)Bptr;

    float cacc[8][8];
    #pragma unroll
    for (int i = 0; i < 8; i++)
        #pragma unroll
        for (int j = 0; j < 8; j++) cacc[i][j] = 0.f;

    const int ktiles = K / BK;
    for (int kt = 0; kt < ktiles; kt++) {
        // commit current regs to smem
        As[lhalf * 4 + 0][lrow] = aReg.x;
        As[lhalf * 4 + 1][lrow] = aReg.y;
        As[lhalf * 4 + 2][lrow] = aReg.z;
        As[lhalf * 4 + 3][lrow] = aReg.w;
        Bs[lhalf * 4 + 0][lrow] = bReg.x;
        Bs[lhalf * 4 + 1][lrow] = bReg.y;
        Bs[lhalf * 4 + 2][lrow] = bReg.z;
        Bs[lhalf * 4 + 3][lrow] = bReg.w;
        __syncthreads();

        // prefetch next k-tile into regs (overlaps with compute below)
        if (kt + 1 < ktiles) {
            aReg = *(const float4*)(Aptr + (size_t)(kt + 1) * BK);
            bReg = *(const float4*)(Bptr + (size_t)(kt + 1) * BK);
        }

        #pragma unroll
        for (int kk = 0; kk < BK; kk++) {
            float af[8], bf[8];
            *(float4*)&af[0] = *(const float4*)&As[kk][ty * 8];
            *(float4*)&af[4] = *(const float4*)&As[kk][ty * 8 + 4];
            *(float4*)&bf[0] = *(const float4*)&Bs[kk][tx * 8];
            *(float4*)&bf[4] = *(const float4*)&Bs[kk][tx * 8 + 4];
            #pragma unroll
            for (int i = 0; i < 8; i++)
                #pragma unroll
                for (int j = 0; j < 8; j++)
                    cacc[i][j] += af[i] * bf[j];
        }
        __syncthreads();
    }

    // epilogue with bias
    float bv[8];
    #pragma unroll
    for (int j = 0; j < 8; j++) bv[j] = bias[n0 + tx * 8 + j];

    #pragma unroll
    for (int i = 0; i < 8; i++) {
        float* Crow = C + (size_t)(m0 + ty * 8 + i) * N + n0 + tx * 8;
        #pragma unroll
        for (int j = 0; j < 8; j++) Crow[j] = cacc[i][j] + bv[j];
    }
}

// ---------------------------------------------------------------------------
// Window attention: one block = (window, head). 196 query rows, one per thread.
// K/V staged in dynamic smem (2 * 196 * 64 floats = 100352 B).
// Online softmax (flash), rescale only when a new max appears.
// Reads q,k,v from g_qkv (raster rows), writes o in raster rows -> proj GEMM
// output is directly the final (B,H,W,C) tensor.
// ---------------------------------------------------------------------------
__global__ __launch_bounds__(224, 1)
void win_attn_kernel(const float* __restrict__ qkv, float* __restrict__ o)
{
    const int head = blockIdx.x;            // 0..11
    const int win  = blockIdx.y;            // 0..255
    const int b  = win >> 4;
    const int hb = (win >> 2) & 3;
    const int wb = win & 3;

    extern __shared__ float sm[];
    float* Ks = sm;                         // [196][64]
    float* Vs = sm + NTOK_ * HD_;           // [196][64]

    // cooperative gather of K and V for this (window, head)
    for (int idx = threadIdx.x; idx < NTOK_ * HD_; idx += blockDim.x) {
        const int n = idx >> 6;
        const int d = idx & 63;
        const int r = n / WS_;
        const int c = n - r * WS_;
        const int row = (b * H_ + hb * WS_ + r) * W_ + (wb * WS_ + c);
        const float* base = qkv + (size_t)row * N_QKV + head * HD_ + d;
        Ks[idx] = base[C_];          // K block at offset 768
        Vs[idx] = base[2 * C_];      // V block at offset 1536
    }
    __syncthreads();

    const int n = threadIdx.x;
    if (n >= NTOK_) return;

    const int r = n / WS_;
    const int c = n - r * WS_;
    const int row = (b * H_ + hb * WS_ + r) * W_ + (wb * WS_ + c);

    const float scale = 0.125f;             // hd^-0.5 = 1/8
    const float* qp = qkv + (size_t)row * N_QKV + head * HD_;

    float q[HD_];
    #pragma unroll
    for (int t = 0; t < 16; t++) {
        float4 v4 = *(const float4*)(qp + 4 * t);
        q[4 * t + 0] = v4.x * scale;
        q[4 * t + 1] = v4.y * scale;
        q[4 * t + 2] = v4.z * scale;
        q[4 * t + 3] = v4.w * scale;
    }

    float m = -1e30f, l = 0.f;
    float acc[HD_];
    #pragma unroll
    for (int d = 0; d < HD_; d++) acc[d] = 0.f;

    for (int j = 0; j < NTOK_; j++) {
        const float4* kj = (const float4*)(Ks + j * HD_);
        float s0 = 0.f, s1 = 0.f, s2 = 0.f, s3 = 0.f;
        #pragma unroll
        for (int t = 0; t < 16; t++) {
            float4 kv = kj[t];
            s0 += q[4 * t + 0] * kv.x;
            s1 += q[4 * t + 1] * kv.y;
            s2 += q[4 * t + 2] * kv.z;
            s3 += q[4 * t + 3] * kv.w;
        }
        const float s = (s0 + s1) + (s2 + s3);
        const float4* vj = (const float4*)(Vs + j * HD_);

        if (s <= m) {
            // common path: no new max, no rescale
            const float p = __expf(s - m);
            l += p;
            #pragma unroll
            for (int t = 0; t < 16; t++) {
                float4 vv = vj[t];
                acc[4 * t + 0] += p * vv.x;
                acc[4 * t + 1] += p * vv.y;
                acc[4 * t + 2] += p * vv.z;
                acc[4 * t + 3] += p * vv.w;
            }
        } else {
            // new max: rescale old state; p == 1 for the current key
            const float sc = __expf(m - s);
            m = s;
            l = l * sc + 1.f;
            #pragma unroll
            for (int t = 0; t < 16; t++) {
                float4 vv = vj[t];
                acc[4 * t + 0] = acc[4 * t + 0] * sc + vv.x;
                acc[4 * t + 1] = acc[4 * t + 1] * sc + vv.y;
                acc[4 * t + 2] = acc[4 * t + 2] * sc + vv.z;
                acc[4 * t + 3] = acc[4 * t + 3] * sc + vv.w;
            }
        }
    }

    const float inv = 1.f / l;
    float* op = o + (size_t)row * C_ + head * HD_;
    #pragma unroll
    for (int t = 0; t < 16; t++) {
        float4 ov;
        ov.x = acc[4 * t + 0] * inv;
        ov.y = acc[4 * t + 1] * inv;
        ov.z = acc[4 * t + 2] * inv;
        ov.w = acc[4 * t + 3] * inv;
        *(float4*)(op + 4 * t) = ov;
    }
}

// ---------------------------------------------------------------------------
extern "C" void kernel_launch(void* const* d_in, const int* in_sizes, int n_in,
                              void* d_out, int out_size)
{
    const float* x      = (const float*)d_in[0];
    const float* qkv_w  = (const float*)d_in[1];
    const float* qkv_b  = (const float*)d_in[2];
    const float* proj_w = (const float*)d_in[3];
    const float* proj_b = (const float*)d_in[4];
    float* out = (float*)d_out;

    float *qkv_s, *o_s;
    cudaGetSymbolAddress((void**)&qkv_s, g_qkv);
    cudaGetSymbolAddress((void**)&o_s,  g_o);

    const int attn_smem = 2 * NTOK_ * HD_ * (int)sizeof(float);  // 100352 B
    cudaFuncSetAttribute(win_attn_kernel,
                         cudaFuncAttributeMaxDynamicSharedMemorySize, attn_smem);

    // 1) QKV GEMM: [50176,768] x [768,2304] (+bias)
    {
        dim3 grid(N_QKV / BN, M_ROWS / BM);   // (18, 392)
        sgemm_nt_bias<<<grid, 256>>>(x, qkv_w, qkv_b, qkv_s, M_ROWS, N_QKV, K_DIM);
    }

    // 2) windowed attention: grid (12 heads, 256 windows)
    {
        dim3 grid(NH_, NWIN_);
        win_attn_kernel<<<grid, 224, attn_smem>>>(qkv_s, o_s);
    }

    // 3) proj GEMM: [50176,768] x [768,768] (+bias) -> final output (raster order)
    {
        dim3 grid(N_PROJ / BN, M_ROWS / BM);  // (6, 392)
        sgemm_nt_bias<<<grid, 256>>>(o_s, proj_w, proj_b, out, M_ROWS, N_PROJ, K_DIM);
    }
}

// round 3
// speedup vs baseline: 2.0924x; 2.0924x over previous
#include <cuda_runtime.h>
#include <cuda_bf16.h>
#include <cstdint>

// ---------------------------------------------------------------------------
// Problem constants
// ---------------------------------------------------------------------------
#define B_       16
#define H_       56
#define W_       56
#define C_       768
#define WS_      14
#define NH_      12
#define HD_      64
#define NTOK_    196
#define NWIN_    256
#define M_ROWS   50176
#define K_DIM    768
#define N_QKV    2304
#define N_PROJ   768

// Scratch (device globals — allocation-free rule)
__device__ float g_qkv[(size_t)M_ROWS * N_QKV];   // QKV output
__device__ float g_o  [(size_t)M_ROWS * N_PROJ];  // attention output (tf32-rounded)
__device__ float g_xr [(size_t)M_ROWS * K_DIM];   // x rounded to tf32
__device__ float g_wq [(size_t)N_QKV  * K_DIM];   // qkv_w rounded to tf32
__device__ float g_wp [(size_t)N_PROJ * K_DIM];   // proj_w rounded to tf32

// ---------------------------------------------------------------------------
// helpers
// ---------------------------------------------------------------------------
__device__ __forceinline__ uint32_t smem_u32(const void* p) {
    uint32_t a;
    asm("{ .reg .u64 t; cvta.to.shared.u64 t, %1; cvt.u32.u64 %0, t; }" : "=r"(a) : "l"(p));
    return a;
}
__device__ __forceinline__ float tf32_rna(float x) {
    uint32_t r;
    asm("cvt.rna.tf32.f32 %0, %1;" : "=r"(r) : "f"(x));
    return __uint_as_float(r);
}
__device__ __forceinline__ void cp_async16(uint32_t dst, const void* src) {
    asm volatile("cp.async.cg.shared.global [%0], [%1], 16;" :: "r"(dst), "l"(src) : "memory");
}
#define CP_COMMIT() asm volatile("cp.async.commit_group;" ::: "memory")
#define CP_WAIT(N)  asm volatile("cp.async.wait_group %0;" :: "n"(N) : "memory")

__device__ __forceinline__ void mma_m16n8k8(float d[4], const uint32_t a[4], const uint32_t b[2]) {
    asm volatile(
        "mma.sync.aligned.m16n8k8.row.col.f32.tf32.tf32.f32 "
        "{%0,%1,%2,%3}, {%4,%5,%6,%7}, {%8,%9}, {%0,%1,%2,%3};"
        : "+f"(d[0]), "+f"(d[1]), "+f"(d[2]), "+f"(d[3])
        : "r"(a[0]), "r"(a[1]), "r"(a[2]), "r"(a[3]), "r"(b[0]), "r"(b[1]));
}

// ---------------------------------------------------------------------------
// tf32 rounding kernel (elementwise, float4)
// ---------------------------------------------------------------------------
__global__ void cvt_tf32_kernel(const float* __restrict__ in, float* __restrict__ out, int n4)
{
    int i = blockIdx.x * blockDim.x + threadIdx.x;
    if (i >= n4) return;
    float4 v = ((const float4*)in)[i];
    v.x = tf32_rna(v.x); v.y = tf32_rna(v.y);
    v.z = tf32_rna(v.z); v.w = tf32_rna(v.w);
    ((float4*)out)[i] = v;
}

// ---------------------------------------------------------------------------
// tf32 mma.sync GEMM (NT): C[m,n] = sum_k A[m,k]*Bt[n,k] + bias[n]
// 128x128x32 tile, 8 warps (warp tile 64x32), cp.async 4-stage pipeline.
// Inputs must already be tf32-rounded (HMMA truncation then exact).
// ---------------------------------------------------------------------------
#define BKG      32
#define STAGES   4
#define ROWPAD   36                        // floats per smem row (bank-conflict-free)
#define TILE_B   (128 * ROWPAD * 4)        // 18432 bytes per tile
#define GEMM_SMEM (2 * STAGES * TILE_B)    // 147456 bytes

__global__ __launch_bounds__(256, 1)
void gemm_tf32_mma(const float* __restrict__ A, const float* __restrict__ Bt,
                   const float* __restrict__ bias, float* __restrict__ C,
                   int M, int N, int K)
{
    extern __shared__ char sm[];
    float* smA = (float*)sm;                        // [STAGES][128][ROWPAD]
    float* smB = (float*)(sm + STAGES * TILE_B);

    const int tid  = threadIdx.x;
    const int wid  = tid >> 5;
    const int lane = tid & 31;
    const int g    = lane >> 2;        // 0..7
    const int t    = lane & 3;         // 0..3
    const int m0   = blockIdx.y * 128;
    const int n0   = blockIdx.x * 128;
    const int wm   = (wid & 1) * 64;   // warp m offset
    const int wn   = (wid >> 1) * 32;  // warp n offset
    const int ktiles = K / BKG;        // 24

    const uint32_t sbA = smem_u32(smA);
    const uint32_t sbB = smem_u32(smB);

    // load assignment: 4 float4 per thread per tile side
    const int lrow0 = tid >> 3;        // f>>3 for i=0 (f=tid)
    const int lc4   = tid & 7;

    auto issue_tile = [&](int kt, int s) {
        const float* Ag = A  + (size_t)m0 * K + (size_t)kt * BKG;
        const float* Bg = Bt + (size_t)n0 * K + (size_t)kt * BKG;
        #pragma unroll
        for (int i = 0; i < 4; i++) {
            const int f   = tid + 256 * i;
            const int row = f >> 3;
            const int c4  = f & 7;
            const uint32_t so = (uint32_t)(s * TILE_B + (row * ROWPAD + c4 * 4) * 4);
            cp_async16(sbA + so, Ag + (size_t)row * K + c4 * 4);
            cp_async16(sbB + so, Bg + (size_t)row * K + c4 * 4);
        }
    };
    (void)lrow0; (void)lc4;

    // prologue: stages 0..2
    issue_tile(0, 0); CP_COMMIT();
    issue_tile(1, 1); CP_COMMIT();
    issue_tile(2, 2); CP_COMMIT();

    float acc[4][4][4];
    #pragma unroll
    for (int i = 0; i < 4; i++)
        #pragma unroll
        for (int j = 0; j < 4; j++)
            #pragma unroll
            for (int r = 0; r < 4; r++) acc[i][j][r] = 0.f;

    for (int kt = 0; kt < ktiles; kt++) {
        __syncthreads();                       // everyone done with stage being overwritten
        if (kt + 3 < ktiles) issue_tile(kt + 3, (kt + 3) % STAGES);
        CP_COMMIT();
        CP_WAIT(3);                            // stage kt%STAGES landed
        __syncthreads();

        const int s = kt % STAGES;
        const float* As = smA + s * (TILE_B / 4);
        const float* Bs = smB + s * (TILE_B / 4);

        #pragma unroll
        for (int kk = 0; kk < 4; kk++) {
            uint32_t a[4][4];
            #pragma unroll
            for (int fm = 0; fm < 4; fm++) {
                const float* p = As + (wm + fm * 16 + g) * ROWPAD + kk * 8 + t;
                a[fm][0] = __float_as_uint(p[0]);
                a[fm][1] = __float_as_uint(p[8 * ROWPAD]);
                a[fm][2] = __float_as_uint(p[4]);
                a[fm][3] = __float_as_uint(p[8 * ROWPAD + 4]);
            }
            uint32_t b[4][2];
            #pragma unroll
            for (int fn = 0; fn < 4; fn++) {
                const float* p = Bs + (wn + fn * 8 + g) * ROWPAD + kk * 8 + t;
                b[fn][0] = __float_as_uint(p[0]);
                b[fn][1] = __float_as_uint(p[4]);
            }
            #pragma unroll
            for (int fm = 0; fm < 4; fm++)
                #pragma unroll
                for (int fn = 0; fn < 4; fn++)
                    mma_m16n8k8(acc[fm][fn], a[fm], b[fn]);
        }
    }
    __syncthreads();

    // epilogue: registers -> C (+bias)
    #pragma unroll
    for (int fm = 0; fm < 4; fm++) {
        const int r0 = m0 + wm + fm * 16 + g;
        #pragma unroll
        for (int fn = 0; fn < 4; fn++) {
            const int c = n0 + wn + fn * 8 + 2 * t;
            const float b0 = bias[c], b1 = bias[c + 1];
            float2 v0 = make_float2(acc[fm][fn][0] + b0, acc[fm][fn][1] + b1);
            float2 v1 = make_float2(acc[fm][fn][2] + b0, acc[fm][fn][3] + b1);
            *(float2*)(C + (size_t)r0 * N + c)       = v0;
            *(float2*)(C + (size_t)(r0 + 8) * N + c) = v1;
        }
    }
}

// ---------------------------------------------------------------------------
// Window attention: one block = (window, head). Emits tf32-rounded output so
// the proj GEMM's A input needs no separate rounding pass.
// ---------------------------------------------------------------------------
__global__ __launch_bounds__(224, 1)
void win_attn_kernel(const float* __restrict__ qkv, float* __restrict__ o)
{
    const int head = blockIdx.x;
    const int win  = blockIdx.y;
    const int b  = win >> 4;
    const int hb = (win >> 2) & 3;
    const int wb = win & 3;

    extern __shared__ float smf[];
    float* Ks = smf;
    float* Vs = smf + NTOK_ * HD_;

    for (int idx = threadIdx.x; idx < NTOK_ * HD_; idx += blockDim.x) {
        const int n = idx >> 6;
        const int d = idx & 63;
        const int r = n / WS_;
        const int c = n - r * WS_;
        const int row = (b * H_ + hb * WS_ + r) * W_ + (wb * WS_ + c);
        const float* base = qkv + (size_t)row * N_QKV + head * HD_ + d;
        Ks[idx] = base[C_];
        Vs[idx] = base[2 * C_];
    }
    __syncthreads();

    const int n = threadIdx.x;
    if (n >= NTOK_) return;

    const int r = n / WS_;
    const int c = n - r * WS_;
    const int row = (b * H_ + hb * WS_ + r) * W_ + (wb * WS_ + c);

    const float scale = 0.125f;
    const float* qp = qkv + (size_t)row * N_QKV + head * HD_;

    float q[HD_];
    #pragma unroll
    for (int tt = 0; tt < 16; tt++) {
        float4 v4 = *(const float4*)(qp + 4 * tt);
        q[4 * tt + 0] = v4.x * scale;
        q[4 * tt + 1] = v4.y * scale;
        q[4 * tt + 2] = v4.z * scale;
        q[4 * tt + 3] = v4.w * scale;
    }

    float m = -1e30f, l = 0.f;
    float acc[HD_];
    #pragma unroll
    for (int d = 0; d < HD_; d++) acc[d] = 0.f;

    for (int j = 0; j < NTOK_; j++) {
        const float4* kj = (const float4*)(Ks + j * HD_);
        float s0 = 0.f, s1 = 0.f, s2 = 0.f, s3 = 0.f;
        #pragma unroll
        for (int tt = 0; tt < 16; tt++) {
            float4 kv = kj[tt];
            s0 += q[4 * tt + 0] * kv.x;
            s1 += q[4 * tt + 1] * kv.y;
            s2 += q[4 * tt + 2] * kv.z;
            s3 += q[4 * tt + 3] * kv.w;
        }
        const float s = (s0 + s1) + (s2 + s3);
        const float4* vj = (const float4*)(Vs + j * HD_);

        if (s <= m) {
            const float p = __expf(s - m);
            l += p;
            #pragma unroll
            for (int tt = 0; tt < 16; tt++) {
                float4 vv = vj[tt];
                acc[4 * tt + 0] += p * vv.x;
                acc[4 * tt + 1] += p * vv.y;
                acc[4 * tt + 2] += p * vv.z;
                acc[4 * tt + 3] += p * vv.w;
            }
        } else {
            const float sc = __expf(m - s);
            m = s;
            l = l * sc + 1.f;
            #pragma unroll
            for (int tt = 0; tt < 16; tt++) {
                float4 vv = vj[tt];
                acc[4 * tt + 0] = acc[4 * tt + 0] * sc + vv.x;
                acc[4 * tt + 1] = acc[4 * tt + 1] * sc + vv.y;
                acc[4 * tt + 2] = acc[4 * tt + 2] * sc + vv.z;
                acc[4 * tt + 3] = acc[4 * tt + 3] * sc + vv.w;
            }
        }
    }

    const float inv = 1.f / l;
    float* op = o + (size_t)row * C_ + head * HD_;
    #pragma unroll
    for (int tt = 0; tt < 16; tt++) {
        float4 ov;
        ov.x = tf32_rna(acc[4 * tt + 0] * inv);
        ov.y = tf32_rna(acc[4 * tt + 1] * inv);
        ov.z = tf32_rna(acc[4 * tt + 2] * inv);
        ov.w = tf32_rna(acc[4 * tt + 3] * inv);
        *(float4*)(op + 4 * tt) = ov;
    }
}

// ---------------------------------------------------------------------------
extern "C" void kernel_launch(void* const* d_in, const int* in_sizes, int n_in,
                              void* d_out, int out_size)
{
    const float* x      = (const float*)d_in[0];
    const float* qkv_w  = (const float*)d_in[1];
    const float* qkv_b  = (const float*)d_in[2];
    const float* proj_w = (const float*)d_in[3];
    const float* proj_b = (const float*)d_in[4];
    float* out = (float*)d_out;

    float *qkv_s, *o_s, *xr, *wq, *wp;
    cudaGetSymbolAddress((void**)&qkv_s, g_qkv);
    cudaGetSymbolAddress((void**)&o_s,   g_o);
    cudaGetSymbolAddress((void**)&xr,    g_xr);
    cudaGetSymbolAddress((void**)&wq,    g_wq);
    cudaGetSymbolAddress((void**)&wp,    g_wp);

    cudaFuncSetAttribute(gemm_tf32_mma,
                         cudaFuncAttributeMaxDynamicSharedMemorySize, GEMM_SMEM);
    const int attn_smem = 2 * NTOK_ * HD_ * (int)sizeof(float);
    cudaFuncSetAttribute(win_attn_kernel,
                         cudaFuncAttributeMaxDynamicSharedMemorySize, attn_smem);

    // 0) round GEMM inputs to tf32 (rna — removes HMMA truncation bias)
    {
        int n4 = M_ROWS * K_DIM / 4;
        cvt_tf32_kernel<<<(n4 + 255) / 256, 256>>>(x, xr, n4);
        n4 = N_QKV * K_DIM / 4;
        cvt_tf32_kernel<<<(n4 + 255) / 256, 256>>>(qkv_w, wq, n4);
        n4 = N_PROJ * K_DIM / 4;
        cvt_tf32_kernel<<<(n4 + 255) / 256, 256>>>(proj_w, wp, n4);
    }

    // 1) QKV GEMM on tensor cores (tf32 mma.sync)
    {
        dim3 grid(N_QKV / 128, M_ROWS / 128);   // (18, 392)
        gemm_tf32_mma<<<grid, 256, GEMM_SMEM>>>(xr, wq, qkv_b, qkv_s,
                                                M_ROWS, N_QKV, K_DIM);
    }

    // 2) windowed attention (fp32, emits tf32-rounded output)
    {
        dim3 grid(NH_, NWIN_);
        win_attn_kernel<<<grid, 224, attn_smem>>>(qkv_s, o_s);
    }

    // 3) proj GEMM -> final output
    {
        dim3 grid(N_PROJ / 128, M_ROWS / 128);  // (6, 392)
        gemm_tf32_mma<<<grid, 256, GEMM_SMEM>>>(o_s, wp, proj_b, out,
                                                M_ROWS, N_PROJ, K_DIM);
    }
}

// round 4
// speedup vs baseline: 3.5044x; 1.6748x over previous
#include <cuda_runtime.h>
#include <cuda_bf16.h>
#include <cstdint>

// ---------------------------------------------------------------------------
// Problem constants
// ---------------------------------------------------------------------------
#define B_       16
#define H_       56
#define W_       56
#define C_       768
#define WS_      14
#define NH_      12
#define HD_      64
#define NTOK_    196
#define NWIN_    256
#define M_ROWS   50176
#define K_DIM    768
#define N_QKV    2304
#define N_PROJ   768

// Scratch (device globals — allocation-free rule)
__device__ float g_qkv[(size_t)M_ROWS * N_QKV];
__device__ float g_o  [(size_t)M_ROWS * N_PROJ];
__device__ float g_xr [(size_t)M_ROWS * K_DIM];
__device__ float g_wq [(size_t)N_QKV  * K_DIM];
__device__ float g_wp [(size_t)N_PROJ * K_DIM];

// ---------------------------------------------------------------------------
// helpers
// ---------------------------------------------------------------------------
__device__ __forceinline__ uint32_t smem_u32(const void* p) {
    uint32_t a;
    asm("{ .reg .u64 t; cvta.to.shared.u64 t, %1; cvt.u32.u64 %0, t; }" : "=r"(a) : "l"(p));
    return a;
}
__device__ __forceinline__ float tf32_rna(float x) {
    uint32_t r;
    asm("cvt.rna.tf32.f32 %0, %1;" : "=r"(r) : "f"(x));
    return __uint_as_float(r);
}
__device__ __forceinline__ float4 rna4(float4 v) {
    v.x = tf32_rna(v.x); v.y = tf32_rna(v.y);
    v.z = tf32_rna(v.z); v.w = tf32_rna(v.w);
    return v;
}
__device__ __forceinline__ void cp_async16(uint32_t dst, const void* src) {
    asm volatile("cp.async.cg.shared.global [%0], [%1], 16;" :: "r"(dst), "l"(src) : "memory");
}
#define CP_COMMIT() asm volatile("cp.async.commit_group;" ::: "memory")
#define CP_WAIT(N)  asm volatile("cp.async.wait_group %0;" :: "n"(N) : "memory")

__device__ __forceinline__ void mma_m16n8k8(float d[4], const uint32_t a[4], const uint32_t b[2]) {
    asm volatile(
        "mma.sync.aligned.m16n8k8.row.col.f32.tf32.tf32.f32 "
        "{%0,%1,%2,%3}, {%4,%5,%6,%7}, {%8,%9}, {%0,%1,%2,%3};"
        : "+f"(d[0]), "+f"(d[1]), "+f"(d[2]), "+f"(d[3])
        : "r"(a[0]), "r"(a[1]), "r"(a[2]), "r"(a[3]), "r"(b[0]), "r"(b[1]));
}

// ---------------------------------------------------------------------------
// tf32 rounding kernel
// ---------------------------------------------------------------------------
__global__ void cvt_tf32_kernel(const float* __restrict__ in, float* __restrict__ out, int n4)
{
    int i = blockIdx.x * blockDim.x + threadIdx.x;
    if (i >= n4) return;
    ((float4*)out)[i] = rna4(((const float4*)in)[i]);
}

// ---------------------------------------------------------------------------
// tf32 mma.sync GEMM (NT), 128x128x32 tile, 3-stage cp.async, 2 CTAs/SM
// ---------------------------------------------------------------------------
#define BKG      32
#define STAGES   3
#define ROWPAD   36
#define TILE_B   (128 * ROWPAD * 4)            // 18432 B
#define GEMM_SMEM (2 * STAGES * TILE_B)        // 110592 B

__global__ __launch_bounds__(256, 2)
void gemm_tf32_mma(const float* __restrict__ A, const float* __restrict__ Bt,
                   const float* __restrict__ bias, float* __restrict__ C,
                   int M, int N, int K)
{
    extern __shared__ char sm[];
    float* smA = (float*)sm;
    float* smB = (float*)(sm + STAGES * TILE_B);

    const int tid  = threadIdx.x;
    const int wid  = tid >> 5;
    const int lane = tid & 31;
    const int g    = lane >> 2;
    const int t    = lane & 3;
    const int m0   = blockIdx.y * 128;
    const int n0   = blockIdx.x * 128;
    const int wm   = (wid & 1) * 64;
    const int wn   = (wid >> 1) * 32;
    const int ktiles = K / BKG;

    const uint32_t sbA = smem_u32(smA);
    const uint32_t sbB = smem_u32(smB);

    auto issue_tile = [&](int kt, int s) {
        const float* Ag = A  + (size_t)m0 * K + (size_t)kt * BKG;
        const float* Bg = Bt + (size_t)n0 * K + (size_t)kt * BKG;
        #pragma unroll
        for (int i = 0; i < 4; i++) {
            const int f   = tid + 256 * i;
            const int row = f >> 3;
            const int c4  = f & 7;
            const uint32_t so = (uint32_t)(s * TILE_B + (row * ROWPAD + c4 * 4) * 4);
            cp_async16(sbA + so, Ag + (size_t)row * K + c4 * 4);
            cp_async16(sbB + so, Bg + (size_t)row * K + c4 * 4);
        }
    };

    issue_tile(0, 0); CP_COMMIT();
    issue_tile(1, 1); CP_COMMIT();

    float acc[4][4][4];
    #pragma unroll
    for (int i = 0; i < 4; i++)
        #pragma unroll
        for (int j = 0; j < 4; j++)
            #pragma unroll
            for (int r = 0; r < 4; r++) acc[i][j][r] = 0.f;

    for (int kt = 0; kt < ktiles; kt++) {
        __syncthreads();
        if (kt + 2 < ktiles) issue_tile(kt + 2, (kt + 2) % STAGES);
        CP_COMMIT();
        CP_WAIT(2);
        __syncthreads();

        const int s = kt % STAGES;
        const float* As = smA + s * (TILE_B / 4);
        const float* Bs = smB + s * (TILE_B / 4);

        #pragma unroll
        for (int kk = 0; kk < 4; kk++) {
            uint32_t a[4][4];
            #pragma unroll
            for (int fm = 0; fm < 4; fm++) {
                const float* p = As + (wm + fm * 16 + g) * ROWPAD + kk * 8 + t;
                a[fm][0] = __float_as_uint(p[0]);
                a[fm][1] = __float_as_uint(p[8 * ROWPAD]);
                a[fm][2] = __float_as_uint(p[4]);
                a[fm][3] = __float_as_uint(p[8 * ROWPAD + 4]);
            }
            uint32_t b[4][2];
            #pragma unroll
            for (int fn = 0; fn < 4; fn++) {
                const float* p = Bs + (wn + fn * 8 + g) * ROWPAD + kk * 8 + t;
                b[fn][0] = __float_as_uint(p[0]);
                b[fn][1] = __float_as_uint(p[4]);
            }
            #pragma unroll
            for (int fm = 0; fm < 4; fm++)
                #pragma unroll
                for (int fn = 0; fn < 4; fn++)
                    mma_m16n8k8(acc[fm][fn], a[fm], b[fn]);
        }
    }
    __syncthreads();

    #pragma unroll
    for (int fm = 0; fm < 4; fm++) {
        const int r0 = m0 + wm + fm * 16 + g;
        #pragma unroll
        for (int fn = 0; fn < 4; fn++) {
            const int c = n0 + wn + fn * 8 + 2 * t;
            const float b0 = bias[c], b1 = bias[c + 1];
            float2 v0 = make_float2(acc[fm][fn][0] + b0, acc[fm][fn][1] + b1);
            float2 v1 = make_float2(acc[fm][fn][2] + b0, acc[fm][fn][3] + b1);
            *(float2*)(C + (size_t)r0 * N + c)       = v0;
            *(float2*)(C + (size_t)(r0 + 8) * N + c) = v1;
        }
    }
}

// ---------------------------------------------------------------------------
// Tensor-core fused window attention.
// Block = (window, head), 256 threads (8 warps), warp = 32 query rows.
// M padded to 256, keys padded to 256, processed in 4 chunks of 64.
// K/V/P in smem (conflict-free pads 68/72/68), Q in registers (a-frags).
// Online softmax on c-frag layout; P round-trips through warp-private smem.
// All mma operands tf32-rna-rounded. Output written tf32-rounded for proj.
// ---------------------------------------------------------------------------
#define KPAD 68
#define VPAD 72
#define PPAD 68
#define AT_SMEM ((256 * KPAD + 256 * VPAD + 8 * 32 * PPAD) * 4)   // 212992 B

__global__ __launch_bounds__(256, 1)
void win_attn_tc(const float* __restrict__ qkv, float* __restrict__ o)
{
    extern __shared__ float s[];
    float* Ks = s;                       // [256][KPAD]
    float* Vs = Ks + 256 * KPAD;         // [256][VPAD]
    float* Ps = Vs + 256 * VPAD;         // [8][32][PPAD]

    const int head = blockIdx.x;
    const int win  = blockIdx.y;
    const int b  = win >> 4;
    const int hb = (win >> 2) & 3;
    const int wb = win & 3;

    const int tid  = threadIdx.x;
    const int w    = tid >> 5;
    const int lane = tid & 31;
    const int g    = lane >> 2;
    const int t    = lane & 3;

    // ---- cooperative K/V fill (zero-padded, tf32-rounded) ----
    for (int idx = tid; idx < 256 * 16; idx += 256) {
        const int n  = idx >> 4;
        const int d4 = (idx & 15) * 4;
        float4 kv = make_float4(0.f, 0.f, 0.f, 0.f);
        float4 vv = kv;
        if (n < NTOK_) {
            const int rr = n / WS_;
            const int cc = n - rr * WS_;
            const size_t row = (size_t)((b * H_ + hb * WS_ + rr) * W_ + (wb * WS_ + cc));
            const float* p = qkv + row * N_QKV + head * HD_ + d4;
            kv = rna4(*(const float4*)(p + C_));
            vv = rna4(*(const float4*)(p + 2 * C_));
        }
        *(float4*)&Ks[n * KPAD + d4] = kv;
        *(float4*)&Vs[n * VPAD + d4] = vv;
    }

    // ---- per-thread raster bases for its 4 query rows ----
    int rb[2][2];
    #pragma unroll
    for (int mt = 0; mt < 2; mt++)
        #pragma unroll
        for (int hf = 0; hf < 2; hf++) {
            const int n = w * 32 + mt * 16 + g + hf * 8;
            if (n < NTOK_) {
                const int rr = n / WS_;
                const int cc = n - rr * WS_;
                rb[mt][hf] = (b * H_ + hb * WS_ + rr) * W_ + (wb * WS_ + cc);
            } else rb[mt][hf] = -1;
        }

    // ---- Q a-frags in registers (pre-scaled, tf32-rounded) ----
    uint32_t q[2][8][4];
    #pragma unroll
    for (int mt = 0; mt < 2; mt++) {
        const float* p0 = (rb[mt][0] >= 0) ? qkv + (size_t)rb[mt][0] * N_QKV + head * HD_ : nullptr;
        const float* p1 = (rb[mt][1] >= 0) ? qkv + (size_t)rb[mt][1] * N_QKV + head * HD_ : nullptr;
        #pragma unroll
        for (int kk = 0; kk < 8; kk++) {
            float v0 = p0 ? p0[kk * 8 + t]     : 0.f;
            float v2 = p0 ? p0[kk * 8 + t + 4] : 0.f;
            float v1 = p1 ? p1[kk * 8 + t]     : 0.f;
            float v3 = p1 ? p1[kk * 8 + t + 4] : 0.f;
            q[mt][kk][0] = __float_as_uint(tf32_rna(v0 * 0.125f));
            q[mt][kk][1] = __float_as_uint(tf32_rna(v1 * 0.125f));
            q[mt][kk][2] = __float_as_uint(tf32_rna(v2 * 0.125f));
            q[mt][kk][3] = __float_as_uint(tf32_rna(v3 * 0.125f));
        }
    }
    __syncthreads();

    float oacc[2][8][4];
    #pragma unroll
    for (int mt = 0; mt < 2; mt++)
        #pragma unroll
        for (int nt = 0; nt < 8; nt++)
            #pragma unroll
            for (int r = 0; r < 4; r++) oacc[mt][nt][r] = 0.f;

    float mrow[2][2] = {{-1e30f, -1e30f}, {-1e30f, -1e30f}};
    float lrow[2][2] = {{0.f, 0.f}, {0.f, 0.f}};
    float* Pw = Ps + w * 32 * PPAD;

    for (int c = 0; c < 4; c++) {
        const int n0c = c * 64;

        // ---- S = Q @ K_chunk^T ----
        float sacc[2][8][4];
        #pragma unroll
        for (int mt = 0; mt < 2; mt++)
            #pragma unroll
            for (int nt = 0; nt < 8; nt++)
                #pragma unroll
                for (int r = 0; r < 4; r++) sacc[mt][nt][r] = 0.f;

        #pragma unroll
        for (int kk = 0; kk < 8; kk++) {
            #pragma unroll
            for (int nt = 0; nt < 8; nt++) {
                const float* kp = Ks + (n0c + nt * 8 + g) * KPAD + kk * 8 + t;
                uint32_t bfr[2];
                bfr[0] = __float_as_uint(kp[0]);
                bfr[1] = __float_as_uint(kp[4]);
                mma_m16n8k8(sacc[0][nt], q[0][kk], bfr);
                mma_m16n8k8(sacc[1][nt], q[1][kk], bfr);
            }
        }

        // ---- mask invalid keys (only last chunk) ----
        if (c == 3) {
            #pragma unroll
            for (int nt = 0; nt < 8; nt++) {
                const int j0 = 192 + nt * 8 + 2 * t;
                if (j0 >= NTOK_)     { sacc[0][nt][0] = -1e30f; sacc[0][nt][2] = -1e30f;
                                       sacc[1][nt][0] = -1e30f; sacc[1][nt][2] = -1e30f; }
                if (j0 + 1 >= NTOK_) { sacc[0][nt][1] = -1e30f; sacc[0][nt][3] = -1e30f;
                                       sacc[1][nt][1] = -1e30f; sacc[1][nt][3] = -1e30f; }
            }
        }

        // ---- online softmax + P store ----
        #pragma unroll
        for (int mt = 0; mt < 2; mt++) {
            float mx0 = -1e30f, mx1 = -1e30f;
            #pragma unroll
            for (int nt = 0; nt < 8; nt++) {
                mx0 = fmaxf(mx0, fmaxf(sacc[mt][nt][0], sacc[mt][nt][1]));
                mx1 = fmaxf(mx1, fmaxf(sacc[mt][nt][2], sacc[mt][nt][3]));
            }
            mx0 = fmaxf(mx0, __shfl_xor_sync(0xffffffffu, mx0, 1));
            mx0 = fmaxf(mx0, __shfl_xor_sync(0xffffffffu, mx0, 2));
            mx1 = fmaxf(mx1, __shfl_xor_sync(0xffffffffu, mx1, 1));
            mx1 = fmaxf(mx1, __shfl_xor_sync(0xffffffffu, mx1, 2));

            const float mn0 = fmaxf(mrow[mt][0], mx0);
            const float mn1 = fmaxf(mrow[mt][1], mx1);
            const float al0 = __expf(mrow[mt][0] - mn0);
            const float al1 = __expf(mrow[mt][1] - mn1);
            mrow[mt][0] = mn0; mrow[mt][1] = mn1;

            float s0 = 0.f, s1 = 0.f;
            float* pr0 = Pw + (mt * 16 + g) * PPAD;
            float* pr1 = pr0 + 8 * PPAD;
            #pragma unroll
            for (int nt = 0; nt < 8; nt++) {
                const float p0 = __expf(sacc[mt][nt][0] - mn0);
                const float p1 = __expf(sacc[mt][nt][1] - mn0);
                const float p2 = __expf(sacc[mt][nt][2] - mn1);
                const float p3 = __expf(sacc[mt][nt][3] - mn1);
                s0 += p0 + p1;
                s1 += p2 + p3;
                *(float2*)&pr0[nt * 8 + 2 * t] = make_float2(tf32_rna(p0), tf32_rna(p1));
                *(float2*)&pr1[nt * 8 + 2 * t] = make_float2(tf32_rna(p2), tf32_rna(p3));
            }
            s0 += __shfl_xor_sync(0xffffffffu, s0, 1);
            s0 += __shfl_xor_sync(0xffffffffu, s0, 2);
            s1 += __shfl_xor_sync(0xffffffffu, s1, 1);
            s1 += __shfl_xor_sync(0xffffffffu, s1, 2);
            lrow[mt][0] = lrow[mt][0] * al0 + s0;
            lrow[mt][1] = lrow[mt][1] * al1 + s1;

            #pragma unroll
            for (int nt = 0; nt < 8; nt++) {
                oacc[mt][nt][0] *= al0; oacc[mt][nt][1] *= al0;
                oacc[mt][nt][2] *= al1; oacc[mt][nt][3] *= al1;
            }
        }
        __syncwarp();

        // ---- O += P_chunk @ V_chunk ----
        #pragma unroll
        for (int kk2 = 0; kk2 < 8; kk2++) {
            uint32_t a[2][4];
            #pragma unroll
            for (int mt = 0; mt < 2; mt++) {
                const float* pp = Pw + (mt * 16 + g) * PPAD + kk2 * 8 + t;
                a[mt][0] = __float_as_uint(pp[0]);
                a[mt][1] = __float_as_uint(pp[8 * PPAD]);
                a[mt][2] = __float_as_uint(pp[4]);
                a[mt][3] = __float_as_uint(pp[8 * PPAD + 4]);
            }
            #pragma unroll
            for (int ntd = 0; ntd < 8; ntd++) {
                const float* vp = Vs + (n0c + kk2 * 8 + t) * VPAD + ntd * 8 + g;
                uint32_t bfr[2];
                bfr[0] = __float_as_uint(vp[0]);
                bfr[1] = __float_as_uint(vp[4 * VPAD]);
                mma_m16n8k8(oacc[0][ntd], a[0], bfr);
                mma_m16n8k8(oacc[1][ntd], a[1], bfr);
            }
        }
        __syncwarp();
    }

    // ---- epilogue: O /= l, tf32-rounded write ----
    #pragma unroll
    for (int mt = 0; mt < 2; mt++) {
        const float i0 = 1.f / lrow[mt][0];
        const float i1 = 1.f / lrow[mt][1];
        if (rb[mt][0] >= 0) {
            float* op = o + (size_t)rb[mt][0] * N_PROJ + head * HD_;
            #pragma unroll
            for (int ntd = 0; ntd < 8; ntd++)
                *(float2*)&op[ntd * 8 + 2 * t] =
                    make_float2(tf32_rna(oacc[mt][ntd][0] * i0), tf32_rna(oacc[mt][ntd][1] * i0));
        }
        if (rb[mt][1] >= 0) {
            float* op = o + (size_t)rb[mt][1] * N_PROJ + head * HD_;
            #pragma unroll
            for (int ntd = 0; ntd < 8; ntd++)
                *(float2*)&op[ntd * 8 + 2 * t] =
                    make_float2(tf32_rna(oacc[mt][ntd][2] * i1), tf32_rna(oacc[mt][ntd][3] * i1));
        }
    }
}

// ---------------------------------------------------------------------------
extern "C" void kernel_launch(void* const* d_in, const int* in_sizes, int n_in,
                              void* d_out, int out_size)
{
    const float* x      = (const float*)d_in[0];
    const float* qkv_w  = (const float*)d_in[1];
    const float* qkv_b  = (const float*)d_in[2];
    const float* proj_w = (const float*)d_in[3];
    const float* proj_b = (const float*)d_in[4];
    float* out = (float*)d_out;

    float *qkv_s, *o_s, *xr, *wq, *wp;
    cudaGetSymbolAddress((void**)&qkv_s, g_qkv);
    cudaGetSymbolAddress((void**)&o_s,   g_o);
    cudaGetSymbolAddress((void**)&xr,    g_xr);
    cudaGetSymbolAddress((void**)&wq,    g_wq);
    cudaGetSymbolAddress((void**)&wp,    g_wp);

    cudaFuncSetAttribute(gemm_tf32_mma,
                         cudaFuncAttributeMaxDynamicSharedMemorySize, GEMM_SMEM);
    cudaFuncSetAttribute(win_attn_tc,
                         cudaFuncAttributeMaxDynamicSharedMemorySize, AT_SMEM);

    // 0) tf32-round GEMM inputs (rna)
    {
        int n4 = M_ROWS * K_DIM / 4;
        cvt_tf32_kernel<<<(n4 + 255) / 256, 256>>>(x, xr, n4);
        n4 = N_QKV * K_DIM / 4;
        cvt_tf32_kernel<<<(n4 + 255) / 256, 256>>>(qkv_w, wq, n4);
        n4 = N_PROJ * K_DIM / 4;
        cvt_tf32_kernel<<<(n4 + 255) / 256, 256>>>(proj_w, wp, n4);
    }

    // 1) QKV GEMM
    {
        dim3 grid(N_QKV / 128, M_ROWS / 128);
        gemm_tf32_mma<<<grid, 256, GEMM_SMEM>>>(xr, wq, qkv_b, qkv_s,
                                                M_ROWS, N_QKV, K_DIM);
    }

    // 2) fused tensor-core window attention
    {
        dim3 grid(NH_, NWIN_);
        win_attn_tc<<<grid, 256, AT_SMEM>>>(qkv_s, o_s);
    }

    // 3) proj GEMM -> final output
    {
        dim3 grid(N_PROJ / 128, M_ROWS / 128);
        gemm_tf32_mma<<<grid, 256, GEMM_SMEM>>>(o_s, wp, proj_b, out,
                                                M_ROWS, N_PROJ, K_DIM);
    }
}

// round 5
// speedup vs baseline: 3.6040x; 1.0284x over previous
#include <cuda_runtime.h>
#include <cuda_bf16.h>
#include <cstdint>

// ---------------------------------------------------------------------------
// Problem constants
// ---------------------------------------------------------------------------
#define B_       16
#define H_       56
#define W_       56
#define C_       768
#define WS_      14
#define NH_      12
#define HD_      64
#define NTOK_    196
#define NWIN_    256
#define M_ROWS   50176
#define K_DIM    768
#define N_QKV    2304
#define N_PROJ   768

// Scratch (device globals — allocation-free rule)
__device__ float g_qkv[(size_t)M_ROWS * N_QKV];
__device__ float g_o  [(size_t)M_ROWS * N_PROJ];
__device__ float g_xr [(size_t)M_ROWS * K_DIM];
__device__ float g_wq [(size_t)N_QKV  * K_DIM];
__device__ float g_wp [(size_t)N_PROJ * K_DIM];

// ---------------------------------------------------------------------------
// helpers
// ---------------------------------------------------------------------------
__device__ __forceinline__ uint32_t smem_u32(const void* p) {
    uint32_t a;
    asm("{ .reg .u64 t; cvta.to.shared.u64 t, %1; cvt.u32.u64 %0, t; }" : "=r"(a) : "l"(p));
    return a;
}
__device__ __forceinline__ float tf32_rna(float x) {
    uint32_t r;
    asm("cvt.rna.tf32.f32 %0, %1;" : "=r"(r) : "f"(x));
    return __uint_as_float(r);
}
__device__ __forceinline__ float4 rna4(float4 v) {
    v.x = tf32_rna(v.x); v.y = tf32_rna(v.y);
    v.z = tf32_rna(v.z); v.w = tf32_rna(v.w);
    return v;
}
__device__ __forceinline__ void cp_async16(uint32_t dst, const void* src) {
    asm volatile("cp.async.cg.shared.global [%0], [%1], 16;" :: "r"(dst), "l"(src) : "memory");
}
#define CP_COMMIT() asm volatile("cp.async.commit_group;" ::: "memory")
#define CP_WAIT(N)  asm volatile("cp.async.wait_group %0;" :: "n"(N) : "memory")

__device__ __forceinline__ void mma_m16n8k8(float d[4], const uint32_t a[4], const uint32_t b[2]) {
    asm volatile(
        "mma.sync.aligned.m16n8k8.row.col.f32.tf32.tf32.f32 "
        "{%0,%1,%2,%3}, {%4,%5,%6,%7}, {%8,%9}, {%0,%1,%2,%3};"
        : "+f"(d[0]), "+f"(d[1]), "+f"(d[2]), "+f"(d[3])
        : "r"(a[0]), "r"(a[1]), "r"(a[2]), "r"(a[3]), "r"(b[0]), "r"(b[1]));
}

// ---------------------------------------------------------------------------
// tf32 rounding kernel
// ---------------------------------------------------------------------------
__global__ void cvt_tf32_kernel(const float* __restrict__ in, float* __restrict__ out, int n4)
{
    int i = blockIdx.x * blockDim.x + threadIdx.x;
    if (i >= n4) return;
    ((float4*)out)[i] = rna4(((const float4*)in)[i]);
}

// ---------------------------------------------------------------------------
// tf32 mma.sync GEMM (NT): 128x128x32 tile, 4 warps (warp tile 64x64),
// 3-stage cp.async pipeline with ONE __syncthreads per k-tile, 2 CTAs/SM.
// ---------------------------------------------------------------------------
#define BKG      32
#define STAGES   3
#define ROWPAD   36
#define TILE_B   (128 * ROWPAD * 4)            // 18432 B
#define GEMM_SMEM (2 * STAGES * TILE_B)        // 110592 B

__global__ __launch_bounds__(128, 2)
void gemm_tf32_mma(const float* __restrict__ A, const float* __restrict__ Bt,
                   const float* __restrict__ bias, float* __restrict__ C,
                   int M, int N, int K)
{
    extern __shared__ char sm[];
    float* smA = (float*)sm;
    float* smB = (float*)(sm + STAGES * TILE_B);

    const int tid  = threadIdx.x;
    const int wid  = tid >> 5;
    const int lane = tid & 31;
    const int g    = lane >> 2;
    const int t    = lane & 3;
    const int m0   = blockIdx.y * 128;
    const int n0   = blockIdx.x * 128;
    const int wm   = (wid & 1) * 64;
    const int wn   = (wid >> 1) * 64;
    const int ktiles = K / BKG;

    const uint32_t sbA = smem_u32(smA);
    const uint32_t sbB = smem_u32(smB);

    auto issue_tile = [&](int kt, int s) {
        const float* Ag = A  + (size_t)m0 * K + (size_t)kt * BKG;
        const float* Bg = Bt + (size_t)n0 * K + (size_t)kt * BKG;
        #pragma unroll
        for (int i = 0; i < 8; i++) {
            const int f   = tid + 128 * i;     // 0..1023 float4 slots
            const int row = f >> 3;
            const int c4  = f & 7;
            const uint32_t so = (uint32_t)(s * TILE_B + (row * ROWPAD + c4 * 4) * 4);
            cp_async16(sbA + so, Ag + (size_t)row * K + c4 * 4);
            cp_async16(sbB + so, Bg + (size_t)row * K + c4 * 4);
        }
    };

    issue_tile(0, 0); CP_COMMIT();
    issue_tile(1, 1); CP_COMMIT();

    float acc[4][8][4];
    #pragma unroll
    for (int i = 0; i < 4; i++)
        #pragma unroll
        for (int j = 0; j < 8; j++)
            #pragma unroll
            for (int r = 0; r < 4; r++) acc[i][j][r] = 0.f;

    for (int kt = 0; kt < ktiles; kt++) {
        CP_WAIT(1);                        // stage kt resident
        __syncthreads();                   // all warps done with stage kt-1
        if (kt + 2 < ktiles)
            issue_tile(kt + 2, (kt + 2) % STAGES);   // overwrites slot (kt-1)%3
        CP_COMMIT();

        const int s = kt % STAGES;
        const float* As = smA + s * (TILE_B / 4);
        const float* Bs = smB + s * (TILE_B / 4);

        #pragma unroll
        for (int kk = 0; kk < 4; kk++) {
            uint32_t a[4][4];
            #pragma unroll
            for (int fm = 0; fm < 4; fm++) {
                const float* p = As + (wm + fm * 16 + g) * ROWPAD + kk * 8 + t;
                a[fm][0] = __float_as_uint(p[0]);
                a[fm][1] = __float_as_uint(p[8 * ROWPAD]);
                a[fm][2] = __float_as_uint(p[4]);
                a[fm][3] = __float_as_uint(p[8 * ROWPAD + 4]);
            }
            uint32_t b[8][2];
            #pragma unroll
            for (int fn = 0; fn < 8; fn++) {
                const float* p = Bs + (wn + fn * 8 + g) * ROWPAD + kk * 8 + t;
                b[fn][0] = __float_as_uint(p[0]);
                b[fn][1] = __float_as_uint(p[4]);
            }
            #pragma unroll
            for (int fm = 0; fm < 4; fm++)
                #pragma unroll
                for (int fn = 0; fn < 8; fn++)
                    mma_m16n8k8(acc[fm][fn], a[fm], b[fn]);
        }
    }
    __syncthreads();

    // epilogue: registers -> C (+bias)
    #pragma unroll
    for (int fm = 0; fm < 4; fm++) {
        const int r0 = m0 + wm + fm * 16 + g;
        #pragma unroll
        for (int fn = 0; fn < 8; fn++) {
            const int c = n0 + wn + fn * 8 + 2 * t;
            const float b0 = bias[c], b1 = bias[c + 1];
            float2 v0 = make_float2(acc[fm][fn][0] + b0, acc[fm][fn][1] + b1);
            float2 v1 = make_float2(acc[fm][fn][2] + b0, acc[fm][fn][3] + b1);
            *(float2*)(C + (size_t)r0 * N + c)       = v0;
            *(float2*)(C + (size_t)(r0 + 8) * N + c) = v1;
        }
    }
}

// ---------------------------------------------------------------------------
// Tensor-core fused window attention (unchanged from R4).
// ---------------------------------------------------------------------------
#define KPAD 68
#define VPAD 72
#define PPAD 68
#define AT_SMEM ((256 * KPAD + 256 * VPAD + 8 * 32 * PPAD) * 4)   // 212992 B

__global__ __launch_bounds__(256, 1)
void win_attn_tc(const float* __restrict__ qkv, float* __restrict__ o)
{
    extern __shared__ float s[];
    float* Ks = s;
    float* Vs = Ks + 256 * KPAD;
    float* Ps = Vs + 256 * VPAD;

    const int head = blockIdx.x;
    const int win  = blockIdx.y;
    const int b  = win >> 4;
    const int hb = (win >> 2) & 3;
    const int wb = win & 3;

    const int tid  = threadIdx.x;
    const int w    = tid >> 5;
    const int lane = tid & 31;
    const int g    = lane >> 2;
    const int t    = lane & 3;

    for (int idx = tid; idx < 256 * 16; idx += 256) {
        const int n  = idx >> 4;
        const int d4 = (idx & 15) * 4;
        float4 kv = make_float4(0.f, 0.f, 0.f, 0.f);
        float4 vv = kv;
        if (n < NTOK_) {
            const int rr = n / WS_;
            const int cc = n - rr * WS_;
            const size_t row = (size_t)((b * H_ + hb * WS_ + rr) * W_ + (wb * WS_ + cc));
            const float* p = qkv + row * N_QKV + head * HD_ + d4;
            kv = rna4(*(const float4*)(p + C_));
            vv = rna4(*(const float4*)(p + 2 * C_));
        }
        *(float4*)&Ks[n * KPAD + d4] = kv;
        *(float4*)&Vs[n * VPAD + d4] = vv;
    }

    int rb[2][2];
    #pragma unroll
    for (int mt = 0; mt < 2; mt++)
        #pragma unroll
        for (int hf = 0; hf < 2; hf++) {
            const int n = w * 32 + mt * 16 + g + hf * 8;
            if (n < NTOK_) {
                const int rr = n / WS_;
                const int cc = n - rr * WS_;
                rb[mt][hf] = (b * H_ + hb * WS_ + rr) * W_ + (wb * WS_ + cc);
            } else rb[mt][hf] = -1;
        }

    uint32_t q[2][8][4];
    #pragma unroll
    for (int mt = 0; mt < 2; mt++) {
        const float* p0 = (rb[mt][0] >= 0) ? qkv + (size_t)rb[mt][0] * N_QKV + head * HD_ : nullptr;
        const float* p1 = (rb[mt][1] >= 0) ? qkv + (size_t)rb[mt][1] * N_QKV + head * HD_ : nullptr;
        #pragma unroll
        for (int kk = 0; kk < 8; kk++) {
            float v0 = p0 ? p0[kk * 8 + t]     : 0.f;
            float v2 = p0 ? p0[kk * 8 + t + 4] : 0.f;
            float v1 = p1 ? p1[kk * 8 + t]     : 0.f;
            float v3 = p1 ? p1[kk * 8 + t + 4] : 0.f;
            q[mt][kk][0] = __float_as_uint(tf32_rna(v0 * 0.125f));
            q[mt][kk][1] = __float_as_uint(tf32_rna(v1 * 0.125f));
            q[mt][kk][2] = __float_as_uint(tf32_rna(v2 * 0.125f));
            q[mt][kk][3] = __float_as_uint(tf32_rna(v3 * 0.125f));
        }
    }
    __syncthreads();

    float oacc[2][8][4];
    #pragma unroll
    for (int mt = 0; mt < 2; mt++)
        #pragma unroll
        for (int nt = 0; nt < 8; nt++)
            #pragma unroll
            for (int r = 0; r < 4; r++) oacc[mt][nt][r] = 0.f;

    float mrow[2][2] = {{-1e30f, -1e30f}, {-1e30f, -1e30f}};
    float lrow[2][2] = {{0.f, 0.f}, {0.f, 0.f}};
    float* Pw = Ps + w * 32 * PPAD;

    for (int c = 0; c < 4; c++) {
        const int n0c = c * 64;

        float sacc[2][8][4];
        #pragma unroll
        for (int mt = 0; mt < 2; mt++)
            #pragma unroll
            for (int nt = 0; nt < 8; nt++)
                #pragma unroll
                for (int r = 0; r < 4; r++) sacc[mt][nt][r] = 0.f;

        #pragma unroll
        for (int kk = 0; kk < 8; kk++) {
            #pragma unroll
            for (int nt = 0; nt < 8; nt++) {
                const float* kp = Ks + (n0c + nt * 8 + g) * KPAD + kk * 8 + t;
                uint32_t bfr[2];
                bfr[0] = __float_as_uint(kp[0]);
                bfr[1] = __float_as_uint(kp[4]);
                mma_m16n8k8(sacc[0][nt], q[0][kk], bfr);
                mma_m16n8k8(sacc[1][nt], q[1][kk], bfr);
            }
        }

        if (c == 3) {
            #pragma unroll
            for (int nt = 0; nt < 8; nt++) {
                const int j0 = 192 + nt * 8 + 2 * t;
                if (j0 >= NTOK_)     { sacc[0][nt][0] = -1e30f; sacc[0][nt][2] = -1e30f;
                                       sacc[1][nt][0] = -1e30f; sacc[1][nt][2] = -1e30f; }
                if (j0 + 1 >= NTOK_) { sacc[0][nt][1] = -1e30f; sacc[0][nt][3] = -1e30f;
                                       sacc[1][nt][1] = -1e30f; sacc[1][nt][3] = -1e30f; }
            }
        }

        #pragma unroll
        for (int mt = 0; mt < 2; mt++) {
            float mx0 = -1e30f, mx1 = -1e30f;
            #pragma unroll
            for (int nt = 0; nt < 8; nt++) {
                mx0 = fmaxf(mx0, fmaxf(sacc[mt][nt][0], sacc[mt][nt][1]));
                mx1 = fmaxf(mx1, fmaxf(sacc[mt][nt][2], sacc[mt][nt][3]));
            }
            mx0 = fmaxf(mx0, __shfl_xor_sync(0xffffffffu, mx0, 1));
            mx0 = fmaxf(mx0, __shfl_xor_sync(0xffffffffu, mx0, 2));
            mx1 = fmaxf(mx1, __shfl_xor_sync(0xffffffffu, mx1, 1));
            mx1 = fmaxf(mx1, __shfl_xor_sync(0xffffffffu, mx1, 2));

            const float mn0 = fmaxf(mrow[mt][0], mx0);
            const float mn1 = fmaxf(mrow[mt][1], mx1);
            const float al0 = __expf(mrow[mt][0] - mn0);
            const float al1 = __expf(mrow[mt][1] - mn1);
            mrow[mt][0] = mn0; mrow[mt][1] = mn1;

            float s0 = 0.f, s1 = 0.f;
            float* pr0 = Pw + (mt * 16 + g) * PPAD;
            float* pr1 = pr0 + 8 * PPAD;
            #pragma unroll
            for (int nt = 0; nt < 8; nt++) {
                const float p0 = __expf(sacc[mt][nt][0] - mn0);
                const float p1 = __expf(sacc[mt][nt][1] - mn0);
                const float p2 = __expf(sacc[mt][nt][2] - mn1);
                const float p3 = __expf(sacc[mt][nt][3] - mn1);
                s0 += p0 + p1;
                s1 += p2 + p3;
                *(float2*)&pr0[nt * 8 + 2 * t] = make_float2(tf32_rna(p0), tf32_rna(p1));
                *(float2*)&pr1[nt * 8 + 2 * t] = make_float2(tf32_rna(p2), tf32_rna(p3));
            }
            s0 += __shfl_xor_sync(0xffffffffu, s0, 1);
            s0 += __shfl_xor_sync(0xffffffffu, s0, 2);
            s1 += __shfl_xor_sync(0xffffffffu, s1, 1);
            s1 += __shfl_xor_sync(0xffffffffu, s1, 2);
            lrow[mt][0] = lrow[mt][0] * al0 + s0;
            lrow[mt][1] = lrow[mt][1] * al1 + s1;

            #pragma unroll
            for (int nt = 0; nt < 8; nt++) {
                oacc[mt][nt][0] *= al0; oacc[mt][nt][1] *= al0;
                oacc[mt][nt][2] *= al1; oacc[mt][nt][3] *= al1;
            }
        }
        __syncwarp();

        #pragma unroll
        for (int kk2 = 0; kk2 < 8; kk2++) {
            uint32_t a[2][4];
            #pragma unroll
            for (int mt = 0; mt < 2; mt++) {
                const float* pp = Pw + (mt * 16 + g) * PPAD + kk2 * 8 + t;
                a[mt][0] = __float_as_uint(pp[0]);
                a[mt][1] = __float_as_uint(pp[8 * PPAD]);
                a[mt][2] = __float_as_uint(pp[4]);
                a[mt][3] = __float_as_uint(pp[8 * PPAD + 4]);
            }
            #pragma unroll
            for (int ntd = 0; ntd < 8; ntd++) {
                const float* vp = Vs + (n0c + kk2 * 8 + t) * VPAD + ntd * 8 + g;
                uint32_t bfr[2];
                bfr[0] = __float_as_uint(vp[0]);
                bfr[1] = __float_as_uint(vp[4 * VPAD]);
                mma_m16n8k8(oacc[0][ntd], a[0], bfr);
                mma_m16n8k8(oacc[1][ntd], a[1], bfr);
            }
        }
        __syncwarp();
    }

    #pragma unroll
    for (int mt = 0; mt < 2; mt++) {
        const float i0 = 1.f / lrow[mt][0];
        const float i1 = 1.f / lrow[mt][1];
        if (rb[mt][0] >= 0) {
            float* op = o + (size_t)rb[mt][0] * N_PROJ + head * HD_;
            #pragma unroll
            for (int ntd = 0; ntd < 8; ntd++)
                *(float2*)&op[ntd * 8 + 2 * t] =
                    make_float2(tf32_rna(oacc[mt][ntd][0] * i0), tf32_rna(oacc[mt][ntd][1] * i0));
        }
        if (rb[mt][1] >= 0) {
            float* op = o + (size_t)rb[mt][1] * N_PROJ + head * HD_;
            #pragma unroll
            for (int ntd = 0; ntd < 8; ntd++)
                *(float2*)&op[ntd * 8 + 2 * t] =
                    make_float2(tf32_rna(oacc[mt][ntd][2] * i1), tf32_rna(oacc[mt][ntd][3] * i1));
        }
    }
}

// ---------------------------------------------------------------------------
extern "C" void kernel_launch(void* const* d_in, const int* in_sizes, int n_in,
                              void* d_out, int out_size)
{
    const float* x      = (const float*)d_in[0];
    const float* qkv_w  = (const float*)d_in[1];
    const float* qkv_b  = (const float*)d_in[2];
    const float* proj_w = (const float*)d_in[3];
    const float* proj_b = (const float*)d_in[4];
    float* out = (float*)d_out;

    float *qkv_s, *o_s, *xr, *wq, *wp;
    cudaGetSymbolAddress((void**)&qkv_s, g_qkv);
    cudaGetSymbolAddress((void**)&o_s,   g_o);
    cudaGetSymbolAddress((void**)&xr,    g_xr);
    cudaGetSymbolAddress((void**)&wq,    g_wq);
    cudaGetSymbolAddress((void**)&wp,    g_wp);

    cudaFuncSetAttribute(gemm_tf32_mma,
                         cudaFuncAttributeMaxDynamicSharedMemorySize, GEMM_SMEM);
    cudaFuncSetAttribute(win_attn_tc,
                         cudaFuncAttributeMaxDynamicSharedMemorySize, AT_SMEM);

    // 0) tf32-round GEMM inputs (rna)
    {
        int n4 = M_ROWS * K_DIM / 4;
        cvt_tf32_kernel<<<(n4 + 255) / 256, 256>>>(x, xr, n4);
        n4 = N_QKV * K_DIM / 4;
        cvt_tf32_kernel<<<(n4 + 255) / 256, 256>>>(qkv_w, wq, n4);
        n4 = N_PROJ * K_DIM / 4;
        cvt_tf32_kernel<<<(n4 + 255) / 256, 256>>>(proj_w, wp, n4);
    }

    // 1) QKV GEMM
    {
        dim3 grid(N_QKV / 128, M_ROWS / 128);
        gemm_tf32_mma<<<grid, 128, GEMM_SMEM>>>(xr, wq, qkv_b, qkv_s,
                                                M_ROWS, N_QKV, K_DIM);
    }

    // 2) fused tensor-core window attention
    {
        dim3 grid(NH_, NWIN_);
        win_attn_tc<<<grid, 256, AT_SMEM>>>(qkv_s, o_s);
    }

    // 3) proj GEMM -> final output
    {
        dim3 grid(N_PROJ / 128, M_ROWS / 128);
        gemm_tf32_mma<<<grid, 128, GEMM_SMEM>>>(o_s, wp, proj_b, out,
                                                M_ROWS, N_PROJ, K_DIM);
    }
}

// round 6
// speedup vs baseline: 3.9382x; 1.0927x over previous
#include <cuda_runtime.h>
#include <cuda_bf16.h>
#include <cstdint>

// ---------------------------------------------------------------------------
// Problem constants
// ---------------------------------------------------------------------------
#define B_       16
#define H_       56
#define W_       56
#define C_       768
#define WS_      14
#define NH_      12
#define HD_      64
#define NTOK_    196
#define NWIN_    256
#define M_ROWS   50176
#define K_DIM    768
#define N_QKV    2304
#define N_PROJ   768

// Scratch (device globals — allocation-free rule)
__device__ float g_qkv[(size_t)M_ROWS * N_QKV];
__device__ float g_o  [(size_t)M_ROWS * N_PROJ];
__device__ float g_xr [(size_t)M_ROWS * K_DIM];
__device__ float g_wq [(size_t)N_QKV  * K_DIM];
__device__ float g_wp [(size_t)N_PROJ * K_DIM];

// ---------------------------------------------------------------------------
// helpers
// ---------------------------------------------------------------------------
__device__ __forceinline__ float tf32_rna(float x) {
    uint32_t r;
    asm("cvt.rna.tf32.f32 %0, %1;" : "=r"(r) : "f"(x));
    return __uint_as_float(r);
}
__device__ __forceinline__ float4 rna4(float4 v) {
    v.x = tf32_rna(v.x); v.y = tf32_rna(v.y);
    v.z = tf32_rna(v.z); v.w = tf32_rna(v.w);
    return v;
}
__device__ __forceinline__ uint32_t smem_u32(const void* p) {
    uint32_t a;
    asm("{ .reg .u64 t; cvta.to.shared.u64 t, %1; cvt.u32.u64 %0, t; }" : "=r"(a) : "l"(p));
    return a;
}
__device__ __forceinline__ void cp_async16(uint32_t dst, const void* src) {
    asm volatile("cp.async.cg.shared.global [%0], [%1], 16;" :: "r"(dst), "l"(src) : "memory");
}
#define CP_COMMIT() asm volatile("cp.async.commit_group;" ::: "memory")
#define CP_WAIT(N)  asm volatile("cp.async.wait_group %0;" :: "n"(N) : "memory")

__device__ __forceinline__ void mma_m16n8k8(float d[4], const uint32_t a[4], const uint32_t b[2]) {
    asm volatile(
        "mma.sync.aligned.m16n8k8.row.col.f32.tf32.tf32.f32 "
        "{%0,%1,%2,%3}, {%4,%5,%6,%7}, {%8,%9}, {%0,%1,%2,%3};"
        : "+f"(d[0]), "+f"(d[1]), "+f"(d[2]), "+f"(d[3])
        : "r"(a[0]), "r"(a[1]), "r"(a[2]), "r"(a[3]), "r"(b[0]), "r"(b[1]));
}

// ---------------------------------------------------------------------------
// tf32 rounding kernel
// ---------------------------------------------------------------------------
__global__ void cvt_tf32_kernel(const float* __restrict__ in, float* __restrict__ out, int n4)
{
    int i = blockIdx.x * blockDim.x + threadIdx.x;
    if (i >= n4) return;
    ((float4*)out)[i] = rna4(((const float4*)in)[i]);
}

// ---------------------------------------------------------------------------
// tf32 mma.sync GEMM (NT): 128x128x32 tile, 8 warps (warp tile 64x32),
// 2-stage cp.async pipeline, one __syncthreads per k-tile, 2 CTAs/SM.
// Fragment loads are LDS.64 via k-slot re-pairing: thread t's two k-slots
// take PHYSICAL columns (2t, 2t+1) for BOTH A and B frags — any consistent
// k-assignment yields the same dot product, and adjacent columns vectorize.
// ROWPAD=40 makes these LDS.64 bank-conflict-free (8g+2t spans all banks).
// ---------------------------------------------------------------------------
#define BKG      32
#define STAGES   2
#define ROWPAD   40
#define TILE_B   (128 * ROWPAD * 4)            // 20480 B
#define GEMM_SMEM (2 * STAGES * TILE_B)        // 81920 B

__global__ __launch_bounds__(256, 2)
void gemm_tf32_mma(const float* __restrict__ A, const float* __restrict__ Bt,
                   const float* __restrict__ bias, float* __restrict__ C,
                   int M, int N, int K)
{
    extern __shared__ char sm[];
    float* smA = (float*)sm;
    float* smB = (float*)(sm + STAGES * TILE_B);

    const int tid  = threadIdx.x;
    const int wid  = tid >> 5;
    const int lane = tid & 31;
    const int g    = lane >> 2;
    const int t    = lane & 3;
    const int m0   = blockIdx.y * 128;
    const int n0   = blockIdx.x * 128;
    const int wm   = (wid & 1) * 64;       // warp m offset
    const int wn   = (wid >> 1) * 32;      // warp n offset (0..96)
    const int ktiles = K / BKG;            // 24

    const uint32_t sbA = smem_u32(smA);
    const uint32_t sbB = smem_u32(smB);

    auto issue_tile = [&](int kt, int s) {
        const float* Ag = A  + (size_t)m0 * K + (size_t)kt * BKG;
        const float* Bg = Bt + (size_t)n0 * K + (size_t)kt * BKG;
        #pragma unroll
        for (int i = 0; i < 4; i++) {
            const int f   = tid + 256 * i;     // 0..1023 float4 slots
            const int row = f >> 3;
            const int c4  = f & 7;
            const uint32_t so = (uint32_t)(s * TILE_B + (row * ROWPAD + c4 * 4) * 4);
            cp_async16(sbA + so, Ag + (size_t)row * K + c4 * 4);
            cp_async16(sbB + so, Bg + (size_t)row * K + c4 * 4);
        }
    };

    issue_tile(0, 0); CP_COMMIT();

    float acc[4][4][4];
    #pragma unroll
    for (int i = 0; i < 4; i++)
        #pragma unroll
        for (int j = 0; j < 4; j++)
            #pragma unroll
            for (int r = 0; r < 4; r++) acc[i][j][r] = 0.f;

    for (int kt = 0; kt < ktiles; kt++) {
        CP_WAIT(0);                         // tile kt fully resident (this thread)
        __syncthreads();                    // all threads' copies visible; prev compute done
        if (kt + 1 < ktiles) {              // overlaps with compute below
            issue_tile(kt + 1, (kt + 1) & 1);
            CP_COMMIT();
        }

        const int s = kt & 1;
        const float* As = smA + s * (TILE_B / 4);
        const float* Bs = smB + s * (TILE_B / 4);

        #pragma unroll
        for (int kk = 0; kk < 4; kk++) {
            // A frags: slots (a0,a2)=(cols 2t,2t+1) row, (a1,a3)= row+8 — LDS.64 each
            uint32_t a[4][4];
            #pragma unroll
            for (int fm = 0; fm < 4; fm++) {
                const int ra = wm + fm * 16 + g;
                const float2 lo = *(const float2*)&As[ra * ROWPAD + kk * 8 + 2 * t];
                const float2 hi = *(const float2*)&As[(ra + 8) * ROWPAD + kk * 8 + 2 * t];
                a[fm][0] = __float_as_uint(lo.x);
                a[fm][1] = __float_as_uint(hi.x);
                a[fm][2] = __float_as_uint(lo.y);
                a[fm][3] = __float_as_uint(hi.y);
            }
            // B frags: (b0,b1)=(cols 2t,2t+1) — single LDS.64
            uint32_t b[4][2];
            #pragma unroll
            for (int fn = 0; fn < 4; fn++) {
                const float2 v = *(const float2*)&Bs[(wn + fn * 8 + g) * ROWPAD + kk * 8 + 2 * t];
                b[fn][0] = __float_as_uint(v.x);
                b[fn][1] = __float_as_uint(v.y);
            }
            #pragma unroll
            for (int fm = 0; fm < 4; fm++)
                #pragma unroll
                for (int fn = 0; fn < 4; fn++)
                    mma_m16n8k8(acc[fm][fn], a[fm], b[fn]);
        }
    }
    __syncthreads();

    // epilogue: registers -> C (+bias)
    #pragma unroll
    for (int fm = 0; fm < 4; fm++) {
        const int r0 = m0 + wm + fm * 16 + g;
        #pragma unroll
        for (int fn = 0; fn < 4; fn++) {
            const int c = n0 + wn + fn * 8 + 2 * t;
            const float b0 = bias[c], b1 = bias[c + 1];
            float2 v0 = make_float2(acc[fm][fn][0] + b0, acc[fm][fn][1] + b1);
            float2 v1 = make_float2(acc[fm][fn][2] + b0, acc[fm][fn][3] + b1);
            *(float2*)(C + (size_t)r0 * N + c)       = v0;
            *(float2*)(C + (size_t)(r0 + 8) * N + c) = v1;
        }
    }
}

// ---------------------------------------------------------------------------
// Tensor-core fused window attention (unchanged from R4/R5).
// ---------------------------------------------------------------------------
#define KPAD 68
#define VPAD 72
#define PPAD 68
#define AT_SMEM ((256 * KPAD + 256 * VPAD + 8 * 32 * PPAD) * 4)   // 212992 B

__global__ __launch_bounds__(256, 1)
void win_attn_tc(const float* __restrict__ qkv, float* __restrict__ o)
{
    extern __shared__ float s[];
    float* Ks = s;
    float* Vs = Ks + 256 * KPAD;
    float* Ps = Vs + 256 * VPAD;

    const int head = blockIdx.x;
    const int win  = blockIdx.y;
    const int b  = win >> 4;
    const int hb = (win >> 2) & 3;
    const int wb = win & 3;

    const int tid  = threadIdx.x;
    const int w    = tid >> 5;
    const int lane = tid & 31;
    const int g    = lane >> 2;
    const int t    = lane & 3;

    for (int idx = tid; idx < 256 * 16; idx += 256) {
        const int n  = idx >> 4;
        const int d4 = (idx & 15) * 4;
        float4 kv = make_float4(0.f, 0.f, 0.f, 0.f);
        float4 vv = kv;
        if (n < NTOK_) {
            const int rr = n / WS_;
            const int cc = n - rr * WS_;
            const size_t row = (size_t)((b * H_ + hb * WS_ + rr) * W_ + (wb * WS_ + cc));
            const float* p = qkv + row * N_QKV + head * HD_ + d4;
            kv = rna4(*(const float4*)(p + C_));
            vv = rna4(*(const float4*)(p + 2 * C_));
        }
        *(float4*)&Ks[n * KPAD + d4] = kv;
        *(float4*)&Vs[n * VPAD + d4] = vv;
    }

    int rb[2][2];
    #pragma unroll
    for (int mt = 0; mt < 2; mt++)
        #pragma unroll
        for (int hf = 0; hf < 2; hf++) {
            const int n = w * 32 + mt * 16 + g + hf * 8;
            if (n < NTOK_) {
                const int rr = n / WS_;
                const int cc = n - rr * WS_;
                rb[mt][hf] = (b * H_ + hb * WS_ + rr) * W_ + (wb * WS_ + cc);
            } else rb[mt][hf] = -1;
        }

    uint32_t q[2][8][4];
    #pragma unroll
    for (int mt = 0; mt < 2; mt++) {
        const float* p0 = (rb[mt][0] >= 0) ? qkv + (size_t)rb[mt][0] * N_QKV + head * HD_ : nullptr;
        const float* p1 = (rb[mt][1] >= 0) ? qkv + (size_t)rb[mt][1] * N_QKV + head * HD_ : nullptr;
        #pragma unroll
        for (int kk = 0; kk < 8; kk++) {
            float v0 = p0 ? p0[kk * 8 + t]     : 0.f;
            float v2 = p0 ? p0[kk * 8 + t + 4] : 0.f;
            float v1 = p1 ? p1[kk * 8 + t]     : 0.f;
            float v3 = p1 ? p1[kk * 8 + t + 4] : 0.f;
            q[mt][kk][0] = __float_as_uint(tf32_rna(v0 * 0.125f));
            q[mt][kk][1] = __float_as_uint(tf32_rna(v1 * 0.125f));
            q[mt][kk][2] = __float_as_uint(tf32_rna(v2 * 0.125f));
            q[mt][kk][3] = __float_as_uint(tf32_rna(v3 * 0.125f));
        }
    }
    __syncthreads();

    float oacc[2][8][4];
    #pragma unroll
    for (int mt = 0; mt < 2; mt++)
        #pragma unroll
        for (int nt = 0; nt < 8; nt++)
            #pragma unroll
            for (int r = 0; r < 4; r++) oacc[mt][nt][r] = 0.f;

    float mrow[2][2] = {{-1e30f, -1e30f}, {-1e30f, -1e30f}};
    float lrow[2][2] = {{0.f, 0.f}, {0.f, 0.f}};
    float* Pw = Ps + w * 32 * PPAD;

    for (int c = 0; c < 4; c++) {
        const int n0c = c * 64;

        float sacc[2][8][4];
        #pragma unroll
        for (int mt = 0; mt < 2; mt++)
            #pragma unroll
            for (int nt = 0; nt < 8; nt++)
                #pragma unroll
                for (int r = 0; r < 4; r++) sacc[mt][nt][r] = 0.f;

        #pragma unroll
        for (int kk = 0; kk < 8; kk++) {
            #pragma unroll
            for (int nt = 0; nt < 8; nt++) {
                const float* kp = Ks + (n0c + nt * 8 + g) * KPAD + kk * 8 + t;
                uint32_t bfr[2];
                bfr[0] = __float_as_uint(kp[0]);
                bfr[1] = __float_as_uint(kp[4]);
                mma_m16n8k8(sacc[0][nt], q[0][kk], bfr);
                mma_m16n8k8(sacc[1][nt], q[1][kk], bfr);
            }
        }

        if (c == 3) {
            #pragma unroll
            for (int nt = 0; nt < 8; nt++) {
                const int j0 = 192 + nt * 8 + 2 * t;
                if (j0 >= NTOK_)     { sacc[0][nt][0] = -1e30f; sacc[0][nt][2] = -1e30f;
                                       sacc[1][nt][0] = -1e30f; sacc[1][nt][2] = -1e30f; }
                if (j0 + 1 >= NTOK_) { sacc[0][nt][1] = -1e30f; sacc[0][nt][3] = -1e30f;
                                       sacc[1][nt][1] = -1e30f; sacc[1][nt][3] = -1e30f; }
            }
        }

        #pragma unroll
        for (int mt = 0; mt < 2; mt++) {
            float mx0 = -1e30f, mx1 = -1e30f;
            #pragma unroll
            for (int nt = 0; nt < 8; nt++) {
                mx0 = fmaxf(mx0, fmaxf(sacc[mt][nt][0], sacc[mt][nt][1]));
                mx1 = fmaxf(mx1, fmaxf(sacc[mt][nt][2], sacc[mt][nt][3]));
            }
            mx0 = fmaxf(mx0, __shfl_xor_sync(0xffffffffu, mx0, 1));
            mx0 = fmaxf(mx0, __shfl_xor_sync(0xffffffffu, mx0, 2));
            mx1 = fmaxf(mx1, __shfl_xor_sync(0xffffffffu, mx1, 1));
            mx1 = fmaxf(mx1, __shfl_xor_sync(0xffffffffu, mx1, 2));

            const float mn0 = fmaxf(mrow[mt][0], mx0);
            const float mn1 = fmaxf(mrow[mt][1], mx1);
            const float al0 = __expf(mrow[mt][0] - mn0);
            const float al1 = __expf(mrow[mt][1] - mn1);
            mrow[mt][0] = mn0; mrow[mt][1] = mn1;

            float s0 = 0.f, s1 = 0.f;
            float* pr0 = Pw + (mt * 16 + g) * PPAD;
            float* pr1 = pr0 + 8 * PPAD;
            #pragma unroll
            for (int nt = 0; nt < 8; nt++) {
                const float p0 = __expf(sacc[mt][nt][0] - mn0);
                const float p1 = __expf(sacc[mt][nt][1] - mn0);
                const float p2 = __expf(sacc[mt][nt][2] - mn1);
                const float p3 = __expf(sacc[mt][nt][3] - mn1);
                s0 += p0 + p1;
                s1 += p2 + p3;
                *(float2*)&pr0[nt * 8 + 2 * t] = make_float2(tf32_rna(p0), tf32_rna(p1));
                *(float2*)&pr1[nt * 8 + 2 * t] = make_float2(tf32_rna(p2), tf32_rna(p3));
            }
            s0 += __shfl_xor_sync(0xffffffffu, s0, 1);
            s0 += __shfl_xor_sync(0xffffffffu, s0, 2);
            s1 += __shfl_xor_sync(0xffffffffu, s1, 1);
            s1 += __shfl_xor_sync(0xffffffffu, s1, 2);
            lrow[mt][0] = lrow[mt][0] * al0 + s0;
            lrow[mt][1] = lrow[mt][1] * al1 + s1;

            #pragma unroll
            for (int nt = 0; nt < 8; nt++) {
                oacc[mt][nt][0] *= al0; oacc[mt][nt][1] *= al0;
                oacc[mt][nt][2] *= al1; oacc[mt][nt][3] *= al1;
            }
        }
        __syncwarp();

        #pragma unroll
        for (int kk2 = 0; kk2 < 8; kk2++) {
            uint32_t a[2][4];
            #pragma unroll
            for (int mt = 0; mt < 2; mt++) {
                const float* pp = Pw + (mt * 16 + g) * PPAD + kk2 * 8 + t;
                a[mt][0] = __float_as_uint(pp[0]);
                a[mt][1] = __float_as_uint(pp[8 * PPAD]);
                a[mt][2] = __float_as_uint(pp[4]);
                a[mt][3] = __float_as_uint(pp[8 * PPAD + 4]);
            }
            #pragma unroll
            for (int ntd = 0; ntd < 8; ntd++) {
                const float* vp = Vs + (n0c + kk2 * 8 + t) * VPAD + ntd * 8 + g;
                uint32_t bfr[2];
                bfr[0] = __float_as_uint(vp[0]);
                bfr[1] = __float_as_uint(vp[4 * VPAD]);
                mma_m16n8k8(oacc[0][ntd], a[0], bfr);
                mma_m16n8k8(oacc[1][ntd], a[1], bfr);
            }
        }
        __syncwarp();
    }

    #pragma unroll
    for (int mt = 0; mt < 2; mt++) {
        const float i0 = 1.f / lrow[mt][0];
        const float i1 = 1.f / lrow[mt][1];
        if (rb[mt][0] >= 0) {
            float* op = o + (size_t)rb[mt][0] * N_PROJ + head * HD_;
            #pragma unroll
            for (int ntd = 0; ntd < 8; ntd++)
                *(float2*)&op[ntd * 8 + 2 * t] =
                    make_float2(tf32_rna(oacc[mt][ntd][0] * i0), tf32_rna(oacc[mt][ntd][1] * i0));
        }
        if (rb[mt][1] >= 0) {
            float* op = o + (size_t)rb[mt][1] * N_PROJ + head * HD_;
            #pragma unroll
            for (int ntd = 0; ntd < 8; ntd++)
                *(float2*)&op[ntd * 8 + 2 * t] =
                    make_float2(tf32_rna(oacc[mt][ntd][2] * i1), tf32_rna(oacc[mt][ntd][3] * i1));
        }
    }
}

// ---------------------------------------------------------------------------
extern "C" void kernel_launch(void* const* d_in, const int* in_sizes, int n_in,
                              void* d_out, int out_size)
{
    const float* x      = (const float*)d_in[0];
    const float* qkv_w  = (const float*)d_in[1];
    const float* qkv_b  = (const float*)d_in[2];
    const float* proj_w = (const float*)d_in[3];
    const float* proj_b = (const float*)d_in[4];
    float* out = (float*)d_out;

    float *qkv_s, *o_s, *xr, *wq, *wp;
    cudaGetSymbolAddress((void**)&qkv_s, g_qkv);
    cudaGetSymbolAddress((void**)&o_s,   g_o);
    cudaGetSymbolAddress((void**)&xr,    g_xr);
    cudaGetSymbolAddress((void**)&wq,    g_wq);
    cudaGetSymbolAddress((void**)&wp,    g_wp);

    cudaFuncSetAttribute(gemm_tf32_mma,
                         cudaFuncAttributeMaxDynamicSharedMemorySize, GEMM_SMEM);
    cudaFuncSetAttribute(win_attn_tc,
                         cudaFuncAttributeMaxDynamicSharedMemorySize, AT_SMEM);

    // 0) tf32-round GEMM inputs (rna)
    {
        int n4 = M_ROWS * K_DIM / 4;
        cvt_tf32_kernel<<<(n4 + 255) / 256, 256>>>(x, xr, n4);
        n4 = N_QKV * K_DIM / 4;
        cvt_tf32_kernel<<<(n4 + 255) / 256, 256>>>(qkv_w, wq, n4);
        n4 = N_PROJ * K_DIM / 4;
        cvt_tf32_kernel<<<(n4 + 255) / 256, 256>>>(proj_w, wp, n4);
    }

    // 1) QKV GEMM
    {
        dim3 grid(N_QKV / 128, M_ROWS / 128);
        gemm_tf32_mma<<<grid, 256, GEMM_SMEM>>>(xr, wq, qkv_b, qkv_s,
                                                M_ROWS, N_QKV, K_DIM);
    }

    // 2) fused tensor-core window attention
    {
        dim3 grid(NH_, NWIN_);
        win_attn_tc<<<grid, 256, AT_SMEM>>>(qkv_s, o_s);
    }

    // 3) proj GEMM -> final output
    {
        dim3 grid(N_PROJ / 128, M_ROWS / 128);
        gemm_tf32_mma<<<grid, 256, GEMM_SMEM>>>(o_s, wp, proj_b, out,
                                                M_ROWS, N_PROJ, K_DIM);
    }
}

// round 7
// speedup vs baseline: 3.9835x; 1.0115x over previous
#include <cuda_runtime.h>
#include <cuda_bf16.h>
#include <cstdint>

// ---------------------------------------------------------------------------
// Problem constants
// ---------------------------------------------------------------------------
#define B_       16
#define H_       56
#define W_       56
#define C_       768
#define WS_      14
#define NH_      12
#define HD_      64
#define NTOK_    196
#define NWIN_    256
#define M_ROWS   50176
#define K_DIM    768
#define N_QKV    2304
#define N_PROJ   768

// Scratch (device globals — allocation-free rule)
__device__ float g_qkv[(size_t)M_ROWS * N_QKV];
__device__ float g_o  [(size_t)M_ROWS * N_PROJ];
__device__ float g_xr [(size_t)M_ROWS * K_DIM];
__device__ float g_wq [(size_t)N_QKV  * K_DIM];
__device__ float g_wp [(size_t)N_PROJ * K_DIM];

// ---------------------------------------------------------------------------
// helpers
// ---------------------------------------------------------------------------
__device__ __forceinline__ float tf32_rna(float x) {
    uint32_t r;
    asm("cvt.rna.tf32.f32 %0, %1;" : "=r"(r) : "f"(x));
    return __uint_as_float(r);
}
__device__ __forceinline__ float4 rna4(float4 v) {
    v.x = tf32_rna(v.x); v.y = tf32_rna(v.y);
    v.z = tf32_rna(v.z); v.w = tf32_rna(v.w);
    return v;
}
__device__ __forceinline__ uint32_t smem_u32(const void* p) {
    uint32_t a;
    asm("{ .reg .u64 t; cvta.to.shared.u64 t, %1; cvt.u32.u64 %0, t; }" : "=r"(a) : "l"(p));
    return a;
}
__device__ __forceinline__ void cp_async16(uint32_t dst, const void* src) {
    asm volatile("cp.async.cg.shared.global [%0], [%1], 16;" :: "r"(dst), "l"(src) : "memory");
}
#define CP_COMMIT() asm volatile("cp.async.commit_group;" ::: "memory")
#define CP_WAIT(N)  asm volatile("cp.async.wait_group %0;" :: "n"(N) : "memory")

__device__ __forceinline__ void mma_m16n8k8(float d[4], const uint32_t a[4], const uint32_t b[2]) {
    asm volatile(
        "mma.sync.aligned.m16n8k8.row.col.f32.tf32.tf32.f32 "
        "{%0,%1,%2,%3}, {%4,%5,%6,%7}, {%8,%9}, {%0,%1,%2,%3};"
        : "+f"(d[0]), "+f"(d[1]), "+f"(d[2]), "+f"(d[3])
        : "r"(a[0]), "r"(a[1]), "r"(a[2]), "r"(a[3]), "r"(b[0]), "r"(b[1]));
}

// ---------------------------------------------------------------------------
// tf32 rounding kernel
// ---------------------------------------------------------------------------
__global__ void cvt_tf32_kernel(const float* __restrict__ in, float* __restrict__ out, int n4)
{
    int i = blockIdx.x * blockDim.x + threadIdx.x;
    if (i >= n4) return;
    ((float4*)out)[i] = rna4(((const float4*)in)[i]);
}

// ---------------------------------------------------------------------------
// tf32 mma.sync GEMM (NT): 128x128x32 CTA tile, 4 warps (warp tile 64x64),
// 2-stage cp.async pipeline, one __syncthreads per k-tile, 2 CTAs/SM.
// LDS.64 fragment loads via k-slot re-pairing (cols 2t,2t+1 for both A & B),
// kk-level fragment DOUBLE BUFFERING to hide LDS latency at 4 warps/CTA.
// ROWPAD=40 keeps LDS.64 bank-conflict-free.
// ---------------------------------------------------------------------------
#define BKG      32
#define STAGES   2
#define ROWPAD   40
#define TILE_B   (128 * ROWPAD * 4)            // 20480 B
#define GEMM_SMEM (2 * STAGES * TILE_B)        // 81920 B

__global__ __launch_bounds__(128, 2)
void gemm_tf32_mma(const float* __restrict__ A, const float* __restrict__ Bt,
                   const float* __restrict__ bias, float* __restrict__ C,
                   int M, int N, int K)
{
    extern __shared__ char sm[];
    float* smA = (float*)sm;
    float* smB = (float*)(sm + STAGES * TILE_B);

    const int tid  = threadIdx.x;
    const int wid  = tid >> 5;
    const int lane = tid & 31;
    const int g    = lane >> 2;
    const int t    = lane & 3;
    const int m0   = blockIdx.y * 128;
    const int n0   = blockIdx.x * 128;
    const int wm   = (wid & 1) * 64;
    const int wn   = (wid >> 1) * 64;
    const int ktiles = K / BKG;            // 24

    const uint32_t sbA = smem_u32(smA);
    const uint32_t sbB = smem_u32(smB);

    auto issue_tile = [&](int kt, int s) {
        const float* Ag = A  + (size_t)m0 * K + (size_t)kt * BKG;
        const float* Bg = Bt + (size_t)n0 * K + (size_t)kt * BKG;
        #pragma unroll
        for (int i = 0; i < 8; i++) {
            const int f   = tid + 128 * i;     // 0..1023 float4 slots
            const int row = f >> 3;
            const int c4  = f & 7;
            const uint32_t so = (uint32_t)(s * TILE_B + (row * ROWPAD + c4 * 4) * 4);
            cp_async16(sbA + so, Ag + (size_t)row * K + c4 * 4);
            cp_async16(sbB + so, Bg + (size_t)row * K + c4 * 4);
        }
    };

    auto load_frags = [&](const float* As, const float* Bs, int kk,
                          uint32_t a[4][4], uint32_t b[8][2]) {
        #pragma unroll
        for (int fm = 0; fm < 4; fm++) {
            const int ra = wm + fm * 16 + g;
            const float2 lo = *(const float2*)&As[ra * ROWPAD + kk * 8 + 2 * t];
            const float2 hi = *(const float2*)&As[(ra + 8) * ROWPAD + kk * 8 + 2 * t];
            a[fm][0] = __float_as_uint(lo.x);
            a[fm][1] = __float_as_uint(hi.x);
            a[fm][2] = __float_as_uint(lo.y);
            a[fm][3] = __float_as_uint(hi.y);
        }
        #pragma unroll
        for (int fn = 0; fn < 8; fn++) {
            const float2 v = *(const float2*)&Bs[(wn + fn * 8 + g) * ROWPAD + kk * 8 + 2 * t];
            b[fn][0] = __float_as_uint(v.x);
            b[fn][1] = __float_as_uint(v.y);
        }
    };

    issue_tile(0, 0); CP_COMMIT();

    float acc[4][8][4];
    #pragma unroll
    for (int i = 0; i < 4; i++)
        #pragma unroll
        for (int j = 0; j < 8; j++)
            #pragma unroll
            for (int r = 0; r < 4; r++) acc[i][j][r] = 0.f;

    for (int kt = 0; kt < ktiles; kt++) {
        CP_WAIT(0);                         // tile kt resident
        __syncthreads();                    // writes visible; prev stage consumed
        if (kt + 1 < ktiles) {
            issue_tile(kt + 1, (kt + 1) & 1);   // overlaps compute below
            CP_COMMIT();
        }

        const int s = kt & 1;
        const float* As = smA + s * (TILE_B / 4);
        const float* Bs = smB + s * (TILE_B / 4);

        uint32_t a[2][4][4], b[2][8][2];
        load_frags(As, Bs, 0, a[0], b[0]);
        #pragma unroll
        for (int kk = 0; kk < 4; kk++) {
            const int cur = kk & 1;
            if (kk < 3) load_frags(As, Bs, kk + 1, a[cur ^ 1], b[cur ^ 1]);
            #pragma unroll
            for (int fm = 0; fm < 4; fm++)
                #pragma unroll
                for (int fn = 0; fn < 8; fn++)
                    mma_m16n8k8(acc[fm][fn], a[cur][fm], b[cur][fn]);
        }
    }
    __syncthreads();

    // epilogue: registers -> C (+bias)
    #pragma unroll
    for (int fm = 0; fm < 4; fm++) {
        const int r0 = m0 + wm + fm * 16 + g;
        #pragma unroll
        for (int fn = 0; fn < 8; fn++) {
            const int c = n0 + wn + fn * 8 + 2 * t;
            const float b0 = bias[c], b1 = bias[c + 1];
            float2 v0 = make_float2(acc[fm][fn][0] + b0, acc[fm][fn][1] + b1);
            float2 v1 = make_float2(acc[fm][fn][2] + b0, acc[fm][fn][3] + b1);
            *(float2*)(C + (size_t)r0 * N + c)       = v0;
            *(float2*)(C + (size_t)(r0 + 8) * N + c) = v1;
        }
    }
}

// ---------------------------------------------------------------------------
// Tensor-core fused window attention.
// Changes vs R6: tail key chunk is 8 keys (192..199, 4 valid) instead of 64,
// and warp 7 (query rows 224..255 — all padding) exits after the fill barrier
// (mainloop is warp-local: no block syncs).
// ---------------------------------------------------------------------------
#define KPAD 68
#define VPAD 72
#define PPAD 68
#define AT_SMEM ((256 * KPAD + 256 * VPAD + 8 * 32 * PPAD) * 4)   // 212992 B

__global__ __launch_bounds__(256, 1)
void win_attn_tc(const float* __restrict__ qkv, float* __restrict__ o)
{
    extern __shared__ float s[];
    float* Ks = s;
    float* Vs = Ks + 256 * KPAD;
    float* Ps = Vs + 256 * VPAD;

    const int head = blockIdx.x;
    const int win  = blockIdx.y;
    const int b  = win >> 4;
    const int hb = (win >> 2) & 3;
    const int wb = win & 3;

    const int tid  = threadIdx.x;
    const int w    = tid >> 5;
    const int lane = tid & 31;
    const int g    = lane >> 2;
    const int t    = lane & 3;

    // K/V fill: only rows 0..199 are ever read (keys 0..199; 196..199 zero)
    for (int idx = tid; idx < 200 * 16; idx += 256) {
        const int n  = idx >> 4;
        const int d4 = (idx & 15) * 4;
        float4 kv = make_float4(0.f, 0.f, 0.f, 0.f);
        float4 vv = kv;
        if (n < NTOK_) {
            const int rr = n / WS_;
            const int cc = n - rr * WS_;
            const size_t row = (size_t)((b * H_ + hb * WS_ + rr) * W_ + (wb * WS_ + cc));
            const float* p = qkv + row * N_QKV + head * HD_ + d4;
            kv = rna4(*(const float4*)(p + C_));
            vv = rna4(*(const float4*)(p + 2 * C_));
        }
        *(float4*)&Ks[n * KPAD + d4] = kv;
        *(float4*)&Vs[n * VPAD + d4] = vv;
    }

    int rb[2][2];
    #pragma unroll
    for (int mt = 0; mt < 2; mt++)
        #pragma unroll
        for (int hf = 0; hf < 2; hf++) {
            const int n = w * 32 + mt * 16 + g + hf * 8;
            if (n < NTOK_) {
                const int rr = n / WS_;
                const int cc = n - rr * WS_;
                rb[mt][hf] = (b * H_ + hb * WS_ + rr) * W_ + (wb * WS_ + cc);
            } else rb[mt][hf] = -1;
        }

    uint32_t q[2][8][4];
    #pragma unroll
    for (int mt = 0; mt < 2; mt++) {
        const float* p0 = (rb[mt][0] >= 0) ? qkv + (size_t)rb[mt][0] * N_QKV + head * HD_ : nullptr;
        const float* p1 = (rb[mt][1] >= 0) ? qkv + (size_t)rb[mt][1] * N_QKV + head * HD_ : nullptr;
        #pragma unroll
        for (int kk = 0; kk < 8; kk++) {
            float v0 = p0 ? p0[kk * 8 + t]     : 0.f;
            float v2 = p0 ? p0[kk * 8 + t + 4] : 0.f;
            float v1 = p1 ? p1[kk * 8 + t]     : 0.f;
            float v3 = p1 ? p1[kk * 8 + t + 4] : 0.f;
            q[mt][kk][0] = __float_as_uint(tf32_rna(v0 * 0.125f));
            q[mt][kk][1] = __float_as_uint(tf32_rna(v1 * 0.125f));
            q[mt][kk][2] = __float_as_uint(tf32_rna(v2 * 0.125f));
            q[mt][kk][3] = __float_as_uint(tf32_rna(v3 * 0.125f));
        }
    }
    __syncthreads();

    if (w == 7) return;                     // rows 224..255 all padding

    float oacc[2][8][4];
    #pragma unroll
    for (int mt = 0; mt < 2; mt++)
        #pragma unroll
        for (int nt = 0; nt < 8; nt++)
            #pragma unroll
            for (int r = 0; r < 4; r++) oacc[mt][nt][r] = 0.f;

    float mrow[2][2] = {{-1e30f, -1e30f}, {-1e30f, -1e30f}};
    float lrow[2][2] = {{0.f, 0.f}, {0.f, 0.f}};
    float* Pw = Ps + w * 32 * PPAD;

    // ---- 3 full chunks of 64 keys (0..191), no masking needed ----
    for (int c = 0; c < 3; c++) {
        const int n0c = c * 64;

        float sacc[2][8][4];
        #pragma unroll
        for (int mt = 0; mt < 2; mt++)
            #pragma unroll
            for (int nt = 0; nt < 8; nt++)
                #pragma unroll
                for (int r = 0; r < 4; r++) sacc[mt][nt][r] = 0.f;

        #pragma unroll
        for (int kk = 0; kk < 8; kk++) {
            #pragma unroll
            for (int nt = 0; nt < 8; nt++) {
                const float* kp = Ks + (n0c + nt * 8 + g) * KPAD + kk * 8 + t;
                uint32_t bfr[2];
                bfr[0] = __float_as_uint(kp[0]);
                bfr[1] = __float_as_uint(kp[4]);
                mma_m16n8k8(sacc[0][nt], q[0][kk], bfr);
                mma_m16n8k8(sacc[1][nt], q[1][kk], bfr);
            }
        }

        #pragma unroll
        for (int mt = 0; mt < 2; mt++) {
            float mx0 = -1e30f, mx1 = -1e30f;
            #pragma unroll
            for (int nt = 0; nt < 8; nt++) {
                mx0 = fmaxf(mx0, fmaxf(sacc[mt][nt][0], sacc[mt][nt][1]));
                mx1 = fmaxf(mx1, fmaxf(sacc[mt][nt][2], sacc[mt][nt][3]));
            }
            mx0 = fmaxf(mx0, __shfl_xor_sync(0xffffffffu, mx0, 1));
            mx0 = fmaxf(mx0, __shfl_xor_sync(0xffffffffu, mx0, 2));
            mx1 = fmaxf(mx1, __shfl_xor_sync(0xffffffffu, mx1, 1));
            mx1 = fmaxf(mx1, __shfl_xor_sync(0xffffffffu, mx1, 2));

            const float mn0 = fmaxf(mrow[mt][0], mx0);
            const float mn1 = fmaxf(mrow[mt][1], mx1);
            const float al0 = __expf(mrow[mt][0] - mn0);
            const float al1 = __expf(mrow[mt][1] - mn1);
            mrow[mt][0] = mn0; mrow[mt][1] = mn1;

            float s0 = 0.f, s1 = 0.f;
            float* pr0 = Pw + (mt * 16 + g) * PPAD;
            float* pr1 = pr0 + 8 * PPAD;
            #pragma unroll
            for (int nt = 0; nt < 8; nt++) {
                const float p0 = __expf(sacc[mt][nt][0] - mn0);
                const float p1 = __expf(sacc[mt][nt][1] - mn0);
                const float p2 = __expf(sacc[mt][nt][2] - mn1);
                const float p3 = __expf(sacc[mt][nt][3] - mn1);
                s0 += p0 + p1;
                s1 += p2 + p3;
                *(float2*)&pr0[nt * 8 + 2 * t] = make_float2(tf32_rna(p0), tf32_rna(p1));
                *(float2*)&pr1[nt * 8 + 2 * t] = make_float2(tf32_rna(p2), tf32_rna(p3));
            }
            s0 += __shfl_xor_sync(0xffffffffu, s0, 1);
            s0 += __shfl_xor_sync(0xffffffffu, s0, 2);
            s1 += __shfl_xor_sync(0xffffffffu, s1, 1);
            s1 += __shfl_xor_sync(0xffffffffu, s1, 2);
            lrow[mt][0] = lrow[mt][0] * al0 + s0;
            lrow[mt][1] = lrow[mt][1] * al1 + s1;

            #pragma unroll
            for (int nt = 0; nt < 8; nt++) {
                oacc[mt][nt][0] *= al0; oacc[mt][nt][1] *= al0;
                oacc[mt][nt][2] *= al1; oacc[mt][nt][3] *= al1;
            }
        }
        __syncwarp();

        #pragma unroll
        for (int kk2 = 0; kk2 < 8; kk2++) {
            uint32_t a[2][4];
            #pragma unroll
            for (int mt = 0; mt < 2; mt++) {
                const float* pp = Pw + (mt * 16 + g) * PPAD + kk2 * 8 + t;
                a[mt][0] = __float_as_uint(pp[0]);
                a[mt][1] = __float_as_uint(pp[8 * PPAD]);
                a[mt][2] = __float_as_uint(pp[4]);
                a[mt][3] = __float_as_uint(pp[8 * PPAD + 4]);
            }
            #pragma unroll
            for (int ntd = 0; ntd < 8; ntd++) {
                const float* vp = Vs + (n0c + kk2 * 8 + t) * VPAD + ntd * 8 + g;
                uint32_t bfr[2];
                bfr[0] = __float_as_uint(vp[0]);
                bfr[1] = __float_as_uint(vp[4 * VPAD]);
                mma_m16n8k8(oacc[0][ntd], a[0], bfr);
                mma_m16n8k8(oacc[1][ntd], a[1], bfr);
            }
        }
        __syncwarp();
    }

    // ---- tail chunk: keys 192..199 (one n-tile, 4 valid keys) ----
    {
        float st[2][4] = {{0.f, 0.f, 0.f, 0.f}, {0.f, 0.f, 0.f, 0.f}};
        #pragma unroll
        for (int kk = 0; kk < 8; kk++) {
            const float* kp = Ks + (192 + g) * KPAD + kk * 8 + t;
            uint32_t bfr[2];
            bfr[0] = __float_as_uint(kp[0]);
            bfr[1] = __float_as_uint(kp[4]);
            mma_m16n8k8(st[0], q[0][kk], bfr);
            mma_m16n8k8(st[1], q[1][kk], bfr);
        }
        const int j0 = 192 + 2 * t;
        #pragma unroll
        for (int mt = 0; mt < 2; mt++) {
            if (j0 >= NTOK_)     { st[mt][0] = -1e30f; st[mt][2] = -1e30f; }
            if (j0 + 1 >= NTOK_) { st[mt][1] = -1e30f; st[mt][3] = -1e30f; }

            float mx0 = fmaxf(st[mt][0], st[mt][1]);
            float mx1 = fmaxf(st[mt][2], st[mt][3]);
            mx0 = fmaxf(mx0, __shfl_xor_sync(0xffffffffu, mx0, 1));
            mx0 = fmaxf(mx0, __shfl_xor_sync(0xffffffffu, mx0, 2));
            mx1 = fmaxf(mx1, __shfl_xor_sync(0xffffffffu, mx1, 1));
            mx1 = fmaxf(mx1, __shfl_xor_sync(0xffffffffu, mx1, 2));

            const float mn0 = fmaxf(mrow[mt][0], mx0);
            const float mn1 = fmaxf(mrow[mt][1], mx1);
            const float al0 = __expf(mrow[mt][0] - mn0);
            const float al1 = __expf(mrow[mt][1] - mn1);
            mrow[mt][0] = mn0; mrow[mt][1] = mn1;

            const float p0 = __expf(st[mt][0] - mn0);
            const float p1 = __expf(st[mt][1] - mn0);
            const float p2 = __expf(st[mt][2] - mn1);
            const float p3 = __expf(st[mt][3] - mn1);
            float s0 = p0 + p1, s1 = p2 + p3;
            float* pr0 = Pw + (mt * 16 + g) * PPAD;
            float* pr1 = pr0 + 8 * PPAD;
            *(float2*)&pr0[2 * t] = make_float2(tf32_rna(p0), tf32_rna(p1));
            *(float2*)&pr1[2 * t] = make_float2(tf32_rna(p2), tf32_rna(p3));

            s0 += __shfl_xor_sync(0xffffffffu, s0, 1);
            s0 += __shfl_xor_sync(0xffffffffu, s0, 2);
            s1 += __shfl_xor_sync(0xffffffffu, s1, 1);
            s1 += __shfl_xor_sync(0xffffffffu, s1, 2);
            lrow[mt][0] = lrow[mt][0] * al0 + s0;
            lrow[mt][1] = lrow[mt][1] * al1 + s1;

            #pragma unroll
            for (int nt = 0; nt < 8; nt++) {
                oacc[mt][nt][0] *= al0; oacc[mt][nt][1] *= al0;
                oacc[mt][nt][2] *= al1; oacc[mt][nt][3] *= al1;
            }
        }
        __syncwarp();

        uint32_t a[2][4];
        #pragma unroll
        for (int mt = 0; mt < 2; mt++) {
            const float* pp = Pw + (mt * 16 + g) * PPAD + t;
            a[mt][0] = __float_as_uint(pp[0]);
            a[mt][1] = __float_as_uint(pp[8 * PPAD]);
            a[mt][2] = __float_as_uint(pp[4]);
            a[mt][3] = __float_as_uint(pp[8 * PPAD + 4]);
        }
        #pragma unroll
        for (int ntd = 0; ntd < 8; ntd++) {
            const float* vp = Vs + (192 + t) * VPAD + ntd * 8 + g;
            uint32_t bfr[2];
            bfr[0] = __float_as_uint(vp[0]);
            bfr[1] = __float_as_uint(vp[4 * VPAD]);
            mma_m16n8k8(oacc[0][ntd], a[0], bfr);
            mma_m16n8k8(oacc[1][ntd], a[1], bfr);
        }
    }

    // ---- epilogue ----
    #pragma unroll
    for (int mt = 0; mt < 2; mt++) {
        const float i0 = 1.f / lrow[mt][0];
        const float i1 = 1.f / lrow[mt][1];
        if (rb[mt][0] >= 0) {
            float* op = o + (size_t)rb[mt][0] * N_PROJ + head * HD_;
            #pragma unroll
            for (int ntd = 0; ntd < 8; ntd++)
                *(float2*)&op[ntd * 8 + 2 * t] =
                    make_float2(tf32_rna(oacc[mt][ntd][0] * i0), tf32_rna(oacc[mt][ntd][1] * i0));
        }
        if (rb[mt][1] >= 0) {
            float* op = o + (size_t)rb[mt][1] * N_PROJ + head * HD_;
            #pragma unroll
            for (int ntd = 0; ntd < 8; ntd++)
                *(float2*)&op[ntd * 8 + 2 * t] =
                    make_float2(tf32_rna(oacc[mt][ntd][2] * i1), tf32_rna(oacc[mt][ntd][3] * i1));
        }
    }
}

// ---------------------------------------------------------------------------
extern "C" void kernel_launch(void* const* d_in, const int* in_sizes, int n_in,
                              void* d_out, int out_size)
{
    const float* x      = (const float*)d_in[0];
    const float* qkv_w  = (const float*)d_in[1];
    const float* qkv_b  = (const float*)d_in[2];
    const float* proj_w = (const float*)d_in[3];
    const float* proj_b = (const float*)d_in[4];
    float* out = (float*)d_out;

    float *qkv_s, *o_s, *xr, *wq, *wp;
    cudaGetSymbolAddress((void**)&qkv_s, g_qkv);
    cudaGetSymbolAddress((void**)&o_s,   g_o);
    cudaGetSymbolAddress((void**)&xr,    g_xr);
    cudaGetSymbolAddress((void**)&wq,    g_wq);
    cudaGetSymbolAddress((void**)&wp,    g_wp);

    cudaFuncSetAttribute(gemm_tf32_mma,
                         cudaFuncAttributeMaxDynamicSharedMemorySize, GEMM_SMEM);
    cudaFuncSetAttribute(win_attn_tc,
                         cudaFuncAttributeMaxDynamicSharedMemorySize, AT_SMEM);

    // 0) tf32-round GEMM inputs (rna)
    {
        int n4 = M_ROWS * K_DIM / 4;
        cvt_tf32_kernel<<<(n4 + 255) / 256, 256>>>(x, xr, n4);
        n4 = N_QKV * K_DIM / 4;
        cvt_tf32_kernel<<<(n4 + 255) / 256, 256>>>(qkv_w, wq, n4);
        n4 = N_PROJ * K_DIM / 4;
        cvt_tf32_kernel<<<(n4 + 255) / 256, 256>>>(proj_w, wp, n4);
    }

    // 1) QKV GEMM
    {
        dim3 grid(N_QKV / 128, M_ROWS / 128);
        gemm_tf32_mma<<<grid, 128, GEMM_SMEM>>>(xr, wq, qkv_b, qkv_s,
                                                M_ROWS, N_QKV, K_DIM);
    }

    // 2) fused tensor-core window attention
    {
        dim3 grid(NH_, NWIN_);
        win_attn_tc<<<grid, 256, AT_SMEM>>>(qkv_s, o_s);
    }

    // 3) proj GEMM -> final output
    {
        dim3 grid(N_PROJ / 128, M_ROWS / 128);
        gemm_tf32_mma<<<grid, 128, GEMM_SMEM>>>(o_s, wp, proj_b, out,
                                                M_ROWS, N_PROJ, K_DIM);
    }
}